// round 11
// baseline (speedup 1.0000x reference)
#include <cuda_runtime.h>
#include <cuda_bf16.h>
#include <cuda_fp16.h>
#include <cstdint>

#define BB 16
#define MM 2048
#define SS 6
#define EE 128
#define LCC 512
#define VV 32000
#define BM (BB*MM)        // 32768
#define VE (VV*EE)
#define BME (BM*EE)
#define NTILES 1536       // 3 k * 512 tiles of 64 rows
#define NCTA 148

// ---------------- static device scratch ----------------
__device__ __half g_mg[3u*BME];     // MLP(bag)*gp, fp16, [k][g][e] (k=0 never stored)
__device__ float g_tb[BB*EE];       // tf@wA1_bottom + bA1
__device__ float g_u[2][BB*EE];
__device__ float g_logits[BM];
__device__ float g_soft[BM];
__device__ uint4 g_wh[2][2048];     // W^T bf16-hi images, swizzled (32KB each)
__device__ uint4 g_wl[2][2048];     // bf16-lo images

// ---------------- helpers ----------------
__device__ __forceinline__ uint32_t smem_u32(const void* p){
    uint32_t a;
    asm("{ .reg .u64 t; cvta.to.shared.u64 t, %1; cvt.u32.u64 %0, t; }" : "=r"(a) : "l"(p));
    return a;
}
__device__ __forceinline__ uint32_t packbf(float hi, float lo){
    uint32_t r;
    asm("cvt.rn.bf16x2.f32 %0, %1, %2;" : "=r"(r) : "f"(hi), "f"(lo));
    return r;
}
// swizzled byte offset of bf16 (r, c) in an Nx128 tile (256B rows); keeps chunk bit 3.
__device__ __forceinline__ int swz(int r, int c){
    int ch = c >> 3;
    ch = (ch & 8) | ((ch ^ r) & 7);
    return r*256 + ch*16 + (c & 7)*2;
}
__device__ __forceinline__ void ldm4(uint32_t addr, uint32_t r[4]){
    asm volatile("ldmatrix.sync.aligned.m8n8.x4.shared.b16 {%0,%1,%2,%3}, [%4];"
        : "=r"(r[0]), "=r"(r[1]), "=r"(r[2]), "=r"(r[3]) : "r"(addr));
}
__device__ __forceinline__ void mma_bf16(float c[4], const uint32_t a[4], uint32_t b0, uint32_t b1){
    asm volatile("mma.sync.aligned.m16n8k16.row.col.f32.bf16.bf16.f32 "
        "{%0,%1,%2,%3}, {%4,%5,%6,%7}, {%8,%9}, {%0,%1,%2,%3};"
        : "+f"(c[0]), "+f"(c[1]), "+f"(c[2]), "+f"(c[3])
        : "r"(a[0]), "r"(a[1]), "r"(a[2]), "r"(a[3]), "r"(b0), "r"(b1));
}

// ---------------- mbarrier ----------------
#define MBAR_INIT(a, c) \
    asm volatile("mbarrier.init.shared.b64 [%0], %1;" :: "r"((uint32_t)(a)), "r"((uint32_t)(c)) : "memory")
#define MBAR_ARRIVE(a) \
    asm volatile("mbarrier.arrive.shared.b64 _, [%0];" :: "r"((uint32_t)(a)) : "memory")
#define MBAR_WAIT(mbar, par) do { \
    uint32_t _m = (uint32_t)(mbar), _p = (uint32_t)(par), _d; \
    asm volatile("{\n\t.reg .pred p;\n\t" \
        "mbarrier.try_wait.parity.acquire.cta.shared::cta.b64 p, [%1], %2;\n\t" \
        "selp.b32 %0, 1, 0, p;\n\t}" : "=r"(_d) : "r"(_m), "r"(_p) : "memory"); \
    if (!_d) { \
        asm volatile("{\n\t.reg .pred P1;\n\t" \
            "WL_%=:\n\t" \
            "mbarrier.try_wait.parity.acquire.cta.shared::cta.b64 P1, [%0], %1, 0x989680;\n\t" \
            "@P1 bra.uni WD_%=;\n\t" \
            "bra.uni WL_%=;\n\t" \
            "WD_%=:\n\t}" :: "r"(_m), "r"(_p) : "memory"); \
    } \
} while(0)

// ---------------- k_prepw: both layers' W^T bf16 hi/lo images ----------------
__global__ void k_prepw(const float* __restrict__ wA1, const float* __restrict__ wA2){
    int n = blockIdx.x, m = blockIdx.y, kk = threadIdx.x;
    const float* W = m ? wA2 : wA1;
    float w = W[kk*EE + n];
    float hf = __bfloat162float(__float2bfloat16(w));
    float lf = w - hf;
    float hn = __shfl_down_sync(0xffffffffu, hf, 1);
    float ln = __shfl_down_sync(0xffffffffu, lf, 1);
    if (!(kk & 1)){
        int off = swz(n, kk);
        *(uint32_t*)((char*)g_wh[m] + off) = packbf(hn, hf);
        *(uint32_t*)((char*)g_wl[m] + off) = packbf(ln, lf);
    }
}

// ---------------- k_init: tb + u0 ----------------
__global__ void k_init(const float* __restrict__ tf, const float* __restrict__ wA1,
                       const float* __restrict__ bA1, const float* __restrict__ q){
    int b = blockIdx.x, j = threadIdx.x;
    float acc = bA1[j];
#pragma unroll 8
    for (int e = 0; e < EE; e++)
        acc += tf[b*EE + e] * wA1[(EE + e)*EE + j];
    g_tb[b*EE + j] = acc;
    g_u[0][b*EE + j] = q[b*EE + j];
}

// ---------------- persistent warp-specialized MLP ----------------
#define SW1H 0
#define SW1L 32768
#define SW2H 65536
#define SW2L 98304
#define SA(s)   (131072 + (s)*32768)
#define SBAR    196608
#define SLOG    196672   // float[4][64] hop-0 logit partials
#define SMEMSZ  197760

// fragment set for one 16-wide K chunk (32 regs)
struct Frag { uint32_t ah[2][4], al[2][4], wh[2][4], wl[2][4]; };

__device__ __forceinline__ void frag_load(Frag& f, uint32_t sAh, uint32_t sAl,
        uint32_t sWh, uint32_t sWl, int wm, int wn, int rsel, int k0){
    ldm4(sAh + swz(wm*32 + rsel,      k0), f.ah[0]);
    ldm4(sAh + swz(wm*32 + 16 + rsel, k0), f.ah[1]);
    ldm4(sAl + swz(wm*32 + rsel,      k0), f.al[0]);
    ldm4(sAl + swz(wm*32 + 16 + rsel, k0), f.al[1]);
    ldm4(sWh + swz(wn*32 + rsel,      k0), f.wh[0]);
    ldm4(sWh + swz(wn*32 + 16 + rsel, k0), f.wh[1]);
    ldm4(sWl + swz(wn*32 + rsel,      k0), f.wl[0]);
    ldm4(sWl + swz(wn*32 + 16 + rsel, k0), f.wl[1]);
}

__device__ __forceinline__ void frag_mma(float acc[2][4][4], const Frag& f){
#pragma unroll
    for (int nt2 = 0; nt2 < 2; nt2++)
#pragma unroll
        for (int mt = 0; mt < 2; mt++){
            mma_bf16(acc[mt][nt2*2],   f.ah[mt], f.wh[nt2][0], f.wh[nt2][2]);
            mma_bf16(acc[mt][nt2*2+1], f.ah[mt], f.wh[nt2][1], f.wh[nt2][3]);
            mma_bf16(acc[mt][nt2*2],   f.ah[mt], f.wl[nt2][0], f.wl[nt2][2]);
            mma_bf16(acc[mt][nt2*2+1], f.ah[mt], f.wl[nt2][1], f.wl[nt2][3]);
            mma_bf16(acc[mt][nt2*2],   f.al[mt], f.wh[nt2][0], f.wh[nt2][2]);
            mma_bf16(acc[mt][nt2*2+1], f.al[mt], f.wh[nt2][1], f.wh[nt2][3]);
        }
}

__device__ __forceinline__ void gemm_fused(uint32_t sAh, uint32_t sAl,
                                           uint32_t sWh, uint32_t sWl,
                                           int wm, int wn, int rsel, int csel,
                                           float acc[2][4][4]){
    Frag f[2];
    frag_load(f[0], sAh, sAl, sWh, sWl, wm, wn, rsel, csel);
#pragma unroll
    for (int ks = 0; ks < 8; ks++){
        if (ks < 7)
            frag_load(f[(ks+1)&1], sAh, sAl, sWh, sWl, wm, wn, rsel, (ks+1)*16 + csel);
        frag_mma(acc, f[ks&1]);
    }
}

__global__ void __launch_bounds__(512, 1)
k_mlp(const int* __restrict__ story, const int* __restrict__ kb_len,
      const int* __restrict__ conv_len, const float* __restrict__ dh,
      const float* __restrict__ C, const float* __restrict__ bA2,
      const float* __restrict__ gp)
{
    extern __shared__ char smem[];
    const uint32_t sb = smem_u32(smem);
    const int tid = threadIdx.x, wid = tid >> 5, lane = tid & 31;
    const int bid = blockIdx.x;

    {
        uint4* s4 = (uint4*)smem;
        for (int i = tid; i < 2048; i += 512){
            s4[i]        = g_wh[0][i];
            s4[i+2048]   = g_wl[0][i];
            s4[i+4096]   = g_wh[1][i];
            s4[i+6144]   = g_wl[1][i];
        }
    }
    if (tid == 0){
        MBAR_INIT(sb + SBAR +  0, 256);   // full[0]
        MBAR_INIT(sb + SBAR +  8, 256);   // full[1]
        MBAR_INIT(sb + SBAR + 16, 256);   // empty[0]
        MBAR_INIT(sb + SBAR + 24, 256);   // empty[1]
    }
    __syncthreads();

    if (wid >= 8){
        // ---------- producer: 8 warps ----------
        const int ptid = tid - 256;
        int it = 0;
        for (int t = bid; t < NTILES; t += NCTA, it++){
            const int s = it & 1;
            const int k = t / 512, g0 = (t & 511) * 64, b = g0 >> 11;
            MBAR_WAIT(sb + SBAR + 16 + s*8, ((it>>1)&1)^1);
            const float* Ck = C + (size_t)k * VE;
            const int kb = __ldg(kb_len + b), cl = __ldg(conv_len + b);
            char* aH = smem + SA(s);
            char* aL = aH + 16384;
#pragma unroll 4
            for (int i = 0; i < 8; i++){
                int item = ptid + (i << 8);
                int r = item >> 5, cq = item & 31;
                int g = g0 + r, m = g & (MM-1);
                const int* st = story + (size_t)g * SS;
                float4 sacc = make_float4(0.f, 0.f, 0.f, 0.f);
#pragma unroll
                for (int j = 0; j < 6; j++){
                    float4 v = __ldg((const float4*)(Ck + (size_t)st[j]*EE) + cq);
                    sacc.x += v.x; sacc.y += v.y; sacc.z += v.z; sacc.w += v.w;
                }
                int idx = m - kb;
                if (idx >= 0 && idx < cl){
                    float4 dv = __ldg((const float4*)(dh + ((size_t)b*LCC + idx)*EE) + cq);
                    sacc.x += dv.x; sacc.y += dv.y; sacc.z += dv.z; sacc.w += dv.w;
                }
                float hx = __bfloat162float(__float2bfloat16(sacc.x));
                float hy = __bfloat162float(__float2bfloat16(sacc.y));
                float hz = __bfloat162float(__float2bfloat16(sacc.z));
                float hw = __bfloat162float(__float2bfloat16(sacc.w));
                int off = swz(r, cq*4);
                uint2 hv, lv;
                hv.x = packbf(hy, hx);           hv.y = packbf(hw, hz);
                lv.x = packbf(sacc.y - hy, sacc.x - hx);
                lv.y = packbf(sacc.w - hw, sacc.z - hz);
                *(uint2*)(aH + off) = hv;
                *(uint2*)(aL + off) = lv;
            }
            MBAR_ARRIVE(sb + SBAR + s*8);
        }
    } else {
        // ---------- consumer: 8 warps ----------
        const int wm = wid & 1, wn = wid >> 1;
        const int rsel = (lane & 7) + (lane & 8);
        const int csel = (lane & 16) >> 1;
        float* slog = (float*)(smem + SLOG);   // [4][64]
        int it = 0;
        for (int t = bid; t < NTILES; t += NCTA, it++){
            const int s = it & 1;
            const int k = t / 512, g0 = (t & 511) * 64, b = g0 >> 11;
            const uint32_t sA = sb + SA(s), sAL = sA + 16384;
            MBAR_WAIT(sb + SBAR + s*8, (it>>1)&1);

            float acc[2][4][4];
#pragma unroll
            for (int mt=0; mt<2; mt++)
#pragma unroll
                for (int nt=0; nt<4; nt++)
#pragma unroll
                    for (int i=0; i<4; i++) acc[mt][nt][i] = 0.f;

            gemm_fused(sA, sAL, sb + SW1H, sb + SW1L, wm, wn, rsel, csel, acc);
            asm volatile("bar.sync 1, 256;" ::: "memory");

            // epilogue 1: +tb, lrelu, bf16-split -> overwrite A slot
#pragma unroll
            for (int nt = 0; nt < 4; nt++){
                int gc = wn*32 + nt*8 + (lane & 3)*2;
                float2 tb = *(const float2*)(g_tb + b*EE + gc);
#pragma unroll
                for (int mt = 0; mt < 2; mt++)
#pragma unroll
                    for (int h = 0; h < 2; h++){
                        int rl = wm*32 + mt*16 + (lane >> 2) + h*8;
                        float y0 = acc[mt][nt][h*2]   + tb.x;
                        float y1 = acc[mt][nt][h*2+1] + tb.y;
                        y0 = y0 > 0.f ? y0 : 0.1f*y0;
                        y1 = y1 > 0.f ? y1 : 0.1f*y1;
                        float h0 = __bfloat162float(__float2bfloat16(y0));
                        float h1 = __bfloat162float(__float2bfloat16(y1));
                        int off = swz(rl, gc);
                        *(uint32_t*)(smem + SA(s) + off)         = packbf(h1, h0);
                        *(uint32_t*)(smem + SA(s) + 16384 + off) = packbf(y1 - h1, y0 - h0);
                    }
            }
            asm volatile("bar.sync 1, 256;" ::: "memory");

#pragma unroll
            for (int mt=0; mt<2; mt++)
#pragma unroll
                for (int nt=0; nt<4; nt++)
#pragma unroll
                    for (int i=0; i<4; i++) acc[mt][nt][i] = 0.f;

            gemm_fused(sA, sAL, sb + SW2H, sb + SW2L, wm, wn, rsel, csel, acc);
            MBAR_ARRIVE(sb + SBAR + 16 + s*8);

            // epilogue 2: +bA2, *gp; k>0 -> g_mg (fp16); k==0 -> hop-0 logits
            if (k != 0){
#pragma unroll
                for (int mt = 0; mt < 2; mt++)
#pragma unroll
                    for (int h = 0; h < 2; h++){
                        int rl = wm*32 + mt*16 + (lane >> 2) + h*8;
                        float gv = __ldg(gp + g0 + rl);
                        __half* op = g_mg + (size_t)k*BME + (size_t)(g0 + rl)*EE;
#pragma unroll
                        for (int nt = 0; nt < 4; nt++){
                            int gc = wn*32 + nt*8 + (lane & 3)*2;
                            float2 bv = *(const float2*)(bA2 + gc);
                            float ox = (acc[mt][nt][h*2]   + bv.x) * gv;
                            float oy = (acc[mt][nt][h*2+1] + bv.y) * gv;
                            *(__half2*)(op + gc) = __floats2half2_rn(ox, oy);
                        }
                    }
            } else {
                // hop-0 logits: lp[row] = sum_col (mg0 * u0), u0 = q
                float lp[4];
#pragma unroll
                for (int mt = 0; mt < 2; mt++)
#pragma unroll
                    for (int h = 0; h < 2; h++){
                        int rl = wm*32 + mt*16 + (lane >> 2) + h*8;
                        float gv = __ldg(gp + g0 + rl);
                        float p = 0.f;
#pragma unroll
                        for (int nt = 0; nt < 4; nt++){
                            int gc = wn*32 + nt*8 + (lane & 3)*2;
                            float2 bv = *(const float2*)(bA2 + gc);
                            float2 u0 = *(const float2*)(g_u[0] + b*EE + gc);
                            float ox = (acc[mt][nt][h*2]   + bv.x) * gv;
                            float oy = (acc[mt][nt][h*2+1] + bv.y) * gv;
                            p += ox*u0.x + oy*u0.y;
                        }
                        lp[mt*2 + h] = p;
                    }
#pragma unroll
                for (int i = 0; i < 4; i++){
                    lp[i] += __shfl_xor_sync(0xffffffffu, lp[i], 1);
                    lp[i] += __shfl_xor_sync(0xffffffffu, lp[i], 2);
                }
                if ((lane & 3) == 0){
#pragma unroll
                    for (int mt = 0; mt < 2; mt++)
#pragma unroll
                        for (int h = 0; h < 2; h++){
                            int rl = wm*32 + mt*16 + (lane >> 2) + h*8;
                            slog[wn*64 + rl] = lp[mt*2 + h];
                        }
                }
                asm volatile("bar.sync 1, 256;" ::: "memory");
                if (tid < 64)
                    g_logits[g0 + tid] = slog[tid] + slog[64+tid] + slog[128+tid] + slog[192+tid];
            }
        }
    }
}

// ---------------- phase 2 ----------------
// hop-0 softmax (logits already produced by k_mlp)
__global__ void k_softmax(float* __restrict__ extra){
    __shared__ float red[512];
    int b = blockIdx.x, tid = threadIdx.x;
    const float* l = g_logits + b*MM;
    float v[4];
#pragma unroll
    for (int i = 0; i < 4; i++) v[i] = l[tid + i*512];
    float mx = fmaxf(fmaxf(v[0], v[1]), fmaxf(v[2], v[3]));
    red[tid] = mx; __syncthreads();
    for (int s = 256; s; s >>= 1){ if (tid < s) red[tid] = fmaxf(red[tid], red[tid+s]); __syncthreads(); }
    mx = red[0]; __syncthreads();
    float e[4], ss = 0.f;
#pragma unroll
    for (int i = 0; i < 4; i++){ e[i] = expf(v[i] - mx); ss += e[i]; }
    red[tid] = ss; __syncthreads();
    for (int s = 256; s; s >>= 1){ if (tid < s) red[tid] += red[tid+s]; __syncthreads(); }
    float inv = 1.f / red[0];
#pragma unroll
    for (int i = 0; i < 4; i++){
        float sv = e[i] * inv;
        g_soft[b*MM + tid + i*512] = sv;
        if (extra) extra[b*MM + tid + i*512] = sv;
    }
}

// fused upart+ufinal: one CTA per batch row, 512 threads (16 warps)
__global__ void __launch_bounds__(512, 1)
k_uupd(int k, int uin, int uout){
    __shared__ float red[16][EE];
    int b = blockIdx.x, tid = threadIdx.x, w = tid >> 5, lane = tid & 31;
    const __half* base = g_mg + (size_t)k*BME + ((size_t)(b*MM + w*128))*EE;
    const float* sp = g_soft + b*MM + w*128;
    float a0=0.f, a1=0.f, a2=0.f, a3=0.f;
#pragma unroll 4
    for (int i = 0; i < 128; i++){
        float s = sp[i];
        uint2 rv = *(const uint2*)(base + (size_t)i*EE + lane*4);
        float2 x0 = __half22float2(*(__half2*)&rv.x);
        float2 x1 = __half22float2(*(__half2*)&rv.y);
        a0 += s*x0.x; a1 += s*x0.y; a2 += s*x1.x; a3 += s*x1.y;
    }
    red[w][lane*4+0] = a0; red[w][lane*4+1] = a1;
    red[w][lane*4+2] = a2; red[w][lane*4+3] = a3;
    __syncthreads();
    if (tid < EE){
        float acc = g_u[uin][b*EE + tid];
#pragma unroll
        for (int i = 0; i < 16; i++) acc += red[i][tid];
        g_u[uout][b*EE + tid] = acc;
    }
}

// fused logits+softmax: one CTA per batch row, 512 threads (16 warps)
__global__ void __launch_bounds__(512, 1)
k_ls(int k, int usel, float* __restrict__ exlog, float* __restrict__ exsoft){
    __shared__ float llog[MM];    // 8KB
    __shared__ float red[512];
    int b = blockIdx.x, tid = threadIdx.x, w = tid >> 5, lane = tid & 31;
    float4 uv = *(const float4*)(g_u[usel] + b*EE + lane*4);
    const __half* base = g_mg + (size_t)k*BME + ((size_t)(b*MM + w*128))*EE;
    for (int i0 = 0; i0 < 128; i0 += 4){
        float p[4];
#pragma unroll
        for (int i = 0; i < 4; i++){
            uint2 rv = *(const uint2*)(base + (size_t)(i0+i)*EE + lane*4);
            float2 x0 = __half22float2(*(__half2*)&rv.x);
            float2 x1 = __half22float2(*(__half2*)&rv.y);
            p[i] = x0.x*uv.x + x0.y*uv.y + x1.x*uv.z + x1.y*uv.w;
        }
#pragma unroll
        for (int i = 0; i < 4; i++)
#pragma unroll
            for (int o = 16; o; o >>= 1) p[i] += __shfl_xor_sync(0xffffffffu, p[i], o);
        if (!lane){
#pragma unroll
            for (int i = 0; i < 4; i++){
                llog[w*128 + i0 + i] = p[i];
                if (exlog) exlog[b*MM + w*128 + i0 + i] = p[i];
            }
        }
    }
    __syncthreads();
    // softmax over llog[0..2047]
    float v[4];
#pragma unroll
    for (int i = 0; i < 4; i++) v[i] = llog[tid + i*512];
    float mx = fmaxf(fmaxf(v[0], v[1]), fmaxf(v[2], v[3]));
    red[tid] = mx; __syncthreads();
    for (int s = 256; s; s >>= 1){ if (tid < s) red[tid] = fmaxf(red[tid], red[tid+s]); __syncthreads(); }
    mx = red[0]; __syncthreads();
    float e[4], ss = 0.f;
#pragma unroll
    for (int i = 0; i < 4; i++){ e[i] = expf(v[i] - mx); ss += e[i]; }
    red[tid] = ss; __syncthreads();
    for (int s = 256; s; s >>= 1){ if (tid < s) red[tid] += red[tid+s]; __syncthreads(); }
    float inv = 1.f / red[0];
#pragma unroll
    for (int i = 0; i < 4; i++){
        float sv = e[i] * inv;
        g_soft[b*MM + tid + i*512] = sv;
        if (exsoft) exsoft[b*MM + tid + i*512] = sv;
    }
}

// ---------------- launch ----------------
extern "C" void kernel_launch(void* const* d_in, const int* in_sizes, int n_in,
                              void* d_out, int out_size){
    const int*   story    = (const int*)  d_in[0];
    const int*   kb_len   = (const int*)  d_in[1];
    const int*   conv_len = (const int*)  d_in[2];
    const float* dh       = (const float*)d_in[4];
    const float* tf       = (const float*)d_in[5];
    const float* q        = (const float*)d_in[6];
    const float* gp       = (const float*)d_in[7];
    const float* C        = (const float*)d_in[8];
    const float* wA1      = (const float*)d_in[9];
    const float* bA1      = (const float*)d_in[10];
    const float* wA2      = (const float*)d_in[11];
    const float* bA2      = (const float*)d_in[12];
    float* out = (float*)d_out;   // [0:BM) prob_soft, [BM:2BM) prob_logits

    cudaFuncSetAttribute(k_mlp, cudaFuncAttributeMaxDynamicSharedMemorySize, SMEMSZ);

    k_prepw <<<dim3(128,2), 128>>>(wA1, wA2);
    k_init  <<<BB, EE>>>(tf, wA1, bA1, q);
    k_mlp   <<<NCTA, 512, SMEMSZ>>>(story, kb_len, conv_len, dh, C, bA2, gp);

    // hop 0: logits fused into k_mlp
    k_softmax<<<BB, 512>>>(nullptr);
    k_uupd   <<<BB, 512>>>(1, 0, 1);          // u1 = u0 + soft0 @ mg1
    // hop 1
    k_ls     <<<BB, 512>>>(1, 1, nullptr, nullptr);
    k_uupd   <<<BB, 512>>>(2, 1, 0);          // u2 = u1 + soft1 @ mg2
    // hop 2 (final outputs)
    k_ls     <<<BB, 512>>>(2, 0, out + BM, out);
}

// round 12
// speedup vs baseline: 1.2386x; 1.2386x over previous
#include <cuda_runtime.h>
#include <cuda_bf16.h>
#include <cuda_fp16.h>
#include <cstdint>

#define BB 16
#define MM 2048
#define SS 6
#define EE 128
#define LCC 512
#define VV 32000
#define BM (BB*MM)        // 32768
#define VE (VV*EE)
#define BME (BM*EE)
#define NTILES 1536       // 3 k * 512 tiles of 64 rows
#define NCTA 148

// ---------------- static device scratch ----------------
__device__ __half g_mg[3u*BME];     // MLP(bag)*gp, fp16, [k][g][e]
__device__ float g_tb[BB*EE];       // tf@wA1_bottom + bA1
__device__ float g_u[2][BB*EE];
__device__ float g_logits[BM];
__device__ float g_soft[BM];
__device__ float g_part[16][BB*EE];
__device__ uint4 g_wh[2][2048];     // W^T bf16-hi images, swizzled (32KB each)
__device__ uint4 g_wl[2][2048];     // bf16-lo images

// ---------------- helpers ----------------
__device__ __forceinline__ uint32_t smem_u32(const void* p){
    uint32_t a;
    asm("{ .reg .u64 t; cvta.to.shared.u64 t, %1; cvt.u32.u64 %0, t; }" : "=r"(a) : "l"(p));
    return a;
}
__device__ __forceinline__ uint32_t packbf(float hi, float lo){
    uint32_t r;
    asm("cvt.rn.bf16x2.f32 %0, %1, %2;" : "=r"(r) : "f"(hi), "f"(lo));
    return r;
}
// swizzled byte offset of bf16 (r, c) in an Nx128 tile (256B rows); keeps chunk bit 3.
__device__ __forceinline__ int swz(int r, int c){
    int ch = c >> 3;
    ch = (ch & 8) | ((ch ^ r) & 7);
    return r*256 + ch*16 + (c & 7)*2;
}
__device__ __forceinline__ void ldm4(uint32_t addr, uint32_t r[4]){
    asm volatile("ldmatrix.sync.aligned.m8n8.x4.shared.b16 {%0,%1,%2,%3}, [%4];"
        : "=r"(r[0]), "=r"(r[1]), "=r"(r[2]), "=r"(r[3]) : "r"(addr));
}
__device__ __forceinline__ void mma_bf16(float c[4], const uint32_t a[4], uint32_t b0, uint32_t b1){
    asm volatile("mma.sync.aligned.m16n8k16.row.col.f32.bf16.bf16.f32 "
        "{%0,%1,%2,%3}, {%4,%5,%6,%7}, {%8,%9}, {%0,%1,%2,%3};"
        : "+f"(c[0]), "+f"(c[1]), "+f"(c[2]), "+f"(c[3])
        : "r"(a[0]), "r"(a[1]), "r"(a[2]), "r"(a[3]), "r"(b0), "r"(b1));
}

// ---------------- mbarrier ----------------
#define MBAR_INIT(a, c) \
    asm volatile("mbarrier.init.shared.b64 [%0], %1;" :: "r"((uint32_t)(a)), "r"((uint32_t)(c)) : "memory")
#define MBAR_ARRIVE(a) \
    asm volatile("mbarrier.arrive.shared.b64 _, [%0];" :: "r"((uint32_t)(a)) : "memory")
#define MBAR_WAIT(mbar, par) do { \
    uint32_t _m = (uint32_t)(mbar), _p = (uint32_t)(par), _d; \
    asm volatile("{\n\t.reg .pred p;\n\t" \
        "mbarrier.try_wait.parity.acquire.cta.shared::cta.b64 p, [%1], %2;\n\t" \
        "selp.b32 %0, 1, 0, p;\n\t}" : "=r"(_d) : "r"(_m), "r"(_p) : "memory"); \
    if (!_d) { \
        asm volatile("{\n\t.reg .pred P1;\n\t" \
            "WL_%=:\n\t" \
            "mbarrier.try_wait.parity.acquire.cta.shared::cta.b64 P1, [%0], %1, 0x989680;\n\t" \
            "@P1 bra.uni WD_%=;\n\t" \
            "bra.uni WL_%=;\n\t" \
            "WD_%=:\n\t}" :: "r"(_m), "r"(_p) : "memory"); \
    } \
} while(0)

// ---------------- k_prepw: both layers' W^T bf16 hi/lo images ----------------
__global__ void k_prepw(const float* __restrict__ wA1, const float* __restrict__ wA2){
    int n = blockIdx.x, m = blockIdx.y, kk = threadIdx.x;
    const float* W = m ? wA2 : wA1;
    float w = W[kk*EE + n];
    float hf = __bfloat162float(__float2bfloat16(w));
    float lf = w - hf;
    float hn = __shfl_down_sync(0xffffffffu, hf, 1);
    float ln = __shfl_down_sync(0xffffffffu, lf, 1);
    if (!(kk & 1)){
        int off = swz(n, kk);
        *(uint32_t*)((char*)g_wh[m] + off) = packbf(hn, hf);
        *(uint32_t*)((char*)g_wl[m] + off) = packbf(ln, lf);
    }
}

// ---------------- k_init: tb + u0 ----------------
__global__ void k_init(const float* __restrict__ tf, const float* __restrict__ wA1,
                       const float* __restrict__ bA1, const float* __restrict__ q){
    int b = blockIdx.x, j = threadIdx.x;
    float acc = bA1[j];
#pragma unroll 8
    for (int e = 0; e < EE; e++)
        acc += tf[b*EE + e] * wA1[(EE + e)*EE + j];
    g_tb[b*EE + j] = acc;
    g_u[0][b*EE + j] = q[b*EE + j];
}

// ---------------- persistent warp-specialized MLP (R10, unchanged) ----------------
#define SW1H 0
#define SW1L 32768
#define SW2H 65536
#define SW2L 98304
#define SA(s)   (131072 + (s)*32768)
#define SBAR    196608
#define SMEMSZ  196672

struct Frag { uint32_t ah[2][4], al[2][4], wh[2][4], wl[2][4]; };

__device__ __forceinline__ void frag_load(Frag& f, uint32_t sAh, uint32_t sAl,
        uint32_t sWh, uint32_t sWl, int wm, int wn, int rsel, int k0){
    ldm4(sAh + swz(wm*32 + rsel,      k0), f.ah[0]);
    ldm4(sAh + swz(wm*32 + 16 + rsel, k0), f.ah[1]);
    ldm4(sAl + swz(wm*32 + rsel,      k0), f.al[0]);
    ldm4(sAl + swz(wm*32 + 16 + rsel, k0), f.al[1]);
    ldm4(sWh + swz(wn*32 + rsel,      k0), f.wh[0]);
    ldm4(sWh + swz(wn*32 + 16 + rsel, k0), f.wh[1]);
    ldm4(sWl + swz(wn*32 + rsel,      k0), f.wl[0]);
    ldm4(sWl + swz(wn*32 + 16 + rsel, k0), f.wl[1]);
}

__device__ __forceinline__ void frag_mma(float acc[2][4][4], const Frag& f){
#pragma unroll
    for (int nt2 = 0; nt2 < 2; nt2++)
#pragma unroll
        for (int mt = 0; mt < 2; mt++){
            mma_bf16(acc[mt][nt2*2],   f.ah[mt], f.wh[nt2][0], f.wh[nt2][2]);
            mma_bf16(acc[mt][nt2*2+1], f.ah[mt], f.wh[nt2][1], f.wh[nt2][3]);
            mma_bf16(acc[mt][nt2*2],   f.ah[mt], f.wl[nt2][0], f.wl[nt2][2]);
            mma_bf16(acc[mt][nt2*2+1], f.ah[mt], f.wl[nt2][1], f.wl[nt2][3]);
            mma_bf16(acc[mt][nt2*2],   f.al[mt], f.wh[nt2][0], f.wh[nt2][2]);
            mma_bf16(acc[mt][nt2*2+1], f.al[mt], f.wh[nt2][1], f.wh[nt2][3]);
        }
}

__device__ __forceinline__ void gemm_fused(uint32_t sAh, uint32_t sAl,
                                           uint32_t sWh, uint32_t sWl,
                                           int wm, int wn, int rsel, int csel,
                                           float acc[2][4][4]){
    Frag f[2];
    frag_load(f[0], sAh, sAl, sWh, sWl, wm, wn, rsel, csel);
#pragma unroll
    for (int ks = 0; ks < 8; ks++){
        if (ks < 7)
            frag_load(f[(ks+1)&1], sAh, sAl, sWh, sWl, wm, wn, rsel, (ks+1)*16 + csel);
        frag_mma(acc, f[ks&1]);
    }
}

__global__ void __launch_bounds__(512, 1)
k_mlp(const int* __restrict__ story, const int* __restrict__ kb_len,
      const int* __restrict__ conv_len, const float* __restrict__ dh,
      const float* __restrict__ C, const float* __restrict__ bA2,
      const float* __restrict__ gp)
{
    extern __shared__ char smem[];
    const uint32_t sb = smem_u32(smem);
    const int tid = threadIdx.x, wid = tid >> 5, lane = tid & 31;
    const int bid = blockIdx.x;

    {
        uint4* s4 = (uint4*)smem;
        for (int i = tid; i < 2048; i += 512){
            s4[i]        = g_wh[0][i];
            s4[i+2048]   = g_wl[0][i];
            s4[i+4096]   = g_wh[1][i];
            s4[i+6144]   = g_wl[1][i];
        }
    }
    if (tid == 0){
        MBAR_INIT(sb + SBAR +  0, 256);   // full[0]
        MBAR_INIT(sb + SBAR +  8, 256);   // full[1]
        MBAR_INIT(sb + SBAR + 16, 256);   // empty[0]
        MBAR_INIT(sb + SBAR + 24, 256);   // empty[1]
    }
    __syncthreads();

    if (wid >= 8){
        // ---------- producer: 8 warps ----------
        const int ptid = tid - 256;
        int it = 0;
        for (int t = bid; t < NTILES; t += NCTA, it++){
            const int s = it & 1;
            const int k = t / 512, g0 = (t & 511) * 64, b = g0 >> 11;
            MBAR_WAIT(sb + SBAR + 16 + s*8, ((it>>1)&1)^1);
            const float* Ck = C + (size_t)k * VE;
            const int kb = __ldg(kb_len + b), cl = __ldg(conv_len + b);
            char* aH = smem + SA(s);
            char* aL = aH + 16384;
#pragma unroll 4
            for (int i = 0; i < 8; i++){
                int item = ptid + (i << 8);
                int r = item >> 5, cq = item & 31;
                int g = g0 + r, m = g & (MM-1);
                const int* st = story + (size_t)g * SS;
                float4 sacc = make_float4(0.f, 0.f, 0.f, 0.f);
#pragma unroll
                for (int j = 0; j < 6; j++){
                    float4 v = __ldg((const float4*)(Ck + (size_t)st[j]*EE) + cq);
                    sacc.x += v.x; sacc.y += v.y; sacc.z += v.z; sacc.w += v.w;
                }
                int idx = m - kb;
                if (idx >= 0 && idx < cl){
                    float4 dv = __ldg((const float4*)(dh + ((size_t)b*LCC + idx)*EE) + cq);
                    sacc.x += dv.x; sacc.y += dv.y; sacc.z += dv.z; sacc.w += dv.w;
                }
                float hx = __bfloat162float(__float2bfloat16(sacc.x));
                float hy = __bfloat162float(__float2bfloat16(sacc.y));
                float hz = __bfloat162float(__float2bfloat16(sacc.z));
                float hw = __bfloat162float(__float2bfloat16(sacc.w));
                int off = swz(r, cq*4);
                uint2 hv, lv;
                hv.x = packbf(hy, hx);           hv.y = packbf(hw, hz);
                lv.x = packbf(sacc.y - hy, sacc.x - hx);
                lv.y = packbf(sacc.w - hw, sacc.z - hz);
                *(uint2*)(aH + off) = hv;
                *(uint2*)(aL + off) = lv;
            }
            MBAR_ARRIVE(sb + SBAR + s*8);
        }
    } else {
        // ---------- consumer: 8 warps ----------
        const int wm = wid & 1, wn = wid >> 1;
        const int rsel = (lane & 7) + (lane & 8);
        const int csel = (lane & 16) >> 1;
        int it = 0;
        for (int t = bid; t < NTILES; t += NCTA, it++){
            const int s = it & 1;
            const int k = t / 512, g0 = (t & 511) * 64, b = g0 >> 11;
            const uint32_t sA = sb + SA(s), sAL = sA + 16384;
            MBAR_WAIT(sb + SBAR + s*8, (it>>1)&1);

            float acc[2][4][4];
#pragma unroll
            for (int mt=0; mt<2; mt++)
#pragma unroll
                for (int nt=0; nt<4; nt++)
#pragma unroll
                    for (int i=0; i<4; i++) acc[mt][nt][i] = 0.f;

            gemm_fused(sA, sAL, sb + SW1H, sb + SW1L, wm, wn, rsel, csel, acc);
            asm volatile("bar.sync 1, 256;" ::: "memory");

            // epilogue 1: +tb, lrelu, bf16-split -> overwrite A slot
#pragma unroll
            for (int nt = 0; nt < 4; nt++){
                int gc = wn*32 + nt*8 + (lane & 3)*2;
                float2 tb = *(const float2*)(g_tb + b*EE + gc);
#pragma unroll
                for (int mt = 0; mt < 2; mt++)
#pragma unroll
                    for (int h = 0; h < 2; h++){
                        int rl = wm*32 + mt*16 + (lane >> 2) + h*8;
                        float y0 = acc[mt][nt][h*2]   + tb.x;
                        float y1 = acc[mt][nt][h*2+1] + tb.y;
                        y0 = y0 > 0.f ? y0 : 0.1f*y0;
                        y1 = y1 > 0.f ? y1 : 0.1f*y1;
                        float h0 = __bfloat162float(__float2bfloat16(y0));
                        float h1 = __bfloat162float(__float2bfloat16(y1));
                        int off = swz(rl, gc);
                        *(uint32_t*)(smem + SA(s) + off)         = packbf(h1, h0);
                        *(uint32_t*)(smem + SA(s) + 16384 + off) = packbf(y1 - h1, y0 - h0);
                    }
            }
            asm volatile("bar.sync 1, 256;" ::: "memory");

#pragma unroll
            for (int mt=0; mt<2; mt++)
#pragma unroll
                for (int nt=0; nt<4; nt++)
#pragma unroll
                    for (int i=0; i<4; i++) acc[mt][nt][i] = 0.f;

            gemm_fused(sA, sAL, sb + SW2H, sb + SW2L, wm, wn, rsel, csel, acc);
            MBAR_ARRIVE(sb + SBAR + 16 + s*8);

            // epilogue 2: +bA2, *gp -> g_mg (fp16)
#pragma unroll
            for (int mt = 0; mt < 2; mt++)
#pragma unroll
                for (int h = 0; h < 2; h++){
                    int rl = wm*32 + mt*16 + (lane >> 2) + h*8;
                    float gv = __ldg(gp + g0 + rl);
                    __half* op = g_mg + (size_t)k*BME + (size_t)(g0 + rl)*EE;
#pragma unroll
                    for (int nt = 0; nt < 4; nt++){
                        int gc = wn*32 + nt*8 + (lane & 3)*2;
                        float2 bv = *(const float2*)(bA2 + gc);
                        float ox = (acc[mt][nt][h*2]   + bv.x) * gv;
                        float oy = (acc[mt][nt][h*2+1] + bv.y) * gv;
                        *(__half2*)(op + gc) = __floats2half2_rn(ox, oy);
                    }
                }
        }
    }
}

// ---------------- phase 2 ----------------
__global__ void k_logits(int k, int usel, float* __restrict__ extra){
    int gw = (blockIdx.x * blockDim.x + threadIdx.x) >> 5;
    int lane = threadIdx.x & 31;
    int g0 = gw * 4;
    int b = g0 >> 11;
    float4 uv = *(const float4*)(g_u[usel] + b*EE + lane*4);
    const __half2* mg = (const __half2*)(g_mg + (size_t)k*BME + (size_t)g0*EE);
    float p[4];
#pragma unroll
    for (int i = 0; i < 4; i++){
        uint2 rv = *(const uint2*)(mg + (size_t)i*64 + lane*2);
        float2 x0 = __half22float2(*(__half2*)&rv.x);
        float2 x1 = __half22float2(*(__half2*)&rv.y);
        p[i] = x0.x*uv.x + x0.y*uv.y + x1.x*uv.z + x1.y*uv.w;
    }
#pragma unroll
    for (int i = 0; i < 4; i++)
#pragma unroll
        for (int o = 16; o; o >>= 1) p[i] += __shfl_xor_sync(0xffffffffu, p[i], o);
    if (!lane){
#pragma unroll
        for (int i = 0; i < 4; i++){
            g_logits[g0+i] = p[i];
            if (extra) extra[g0+i] = p[i];
        }
    }
}

// fast softmax: warp-shuffle reductions, 4 __syncthreads total
__global__ void k_softmax(float* __restrict__ extra){
    __shared__ float wred[16];
    __shared__ float bc;
    int b = blockIdx.x, tid = threadIdx.x, w = tid >> 5, lane = tid & 31;
    const float* l = g_logits + b*MM;
    float v[4];
#pragma unroll
    for (int i = 0; i < 4; i++) v[i] = l[tid + i*512];
    float mx = fmaxf(fmaxf(v[0], v[1]), fmaxf(v[2], v[3]));
#pragma unroll
    for (int o = 16; o; o >>= 1) mx = fmaxf(mx, __shfl_xor_sync(0xffffffffu, mx, o));
    if (!lane) wred[w] = mx;
    __syncthreads();
    if (tid < 32){
        float m = (lane < 16) ? wred[lane] : -3.4e38f;
#pragma unroll
        for (int o = 8; o; o >>= 1) m = fmaxf(m, __shfl_xor_sync(0xffffffffu, m, o));
        if (!lane) bc = m;
    }
    __syncthreads();
    mx = bc;
    float e[4], ss = 0.f;
#pragma unroll
    for (int i = 0; i < 4; i++){ e[i] = expf(v[i] - mx); ss += e[i]; }
#pragma unroll
    for (int o = 16; o; o >>= 1) ss += __shfl_xor_sync(0xffffffffu, ss, o);
    if (!lane) wred[w] = ss;
    __syncthreads();
    if (tid < 32){
        float m = (lane < 16) ? wred[lane] : 0.f;
#pragma unroll
        for (int o = 8; o; o >>= 1) m += __shfl_xor_sync(0xffffffffu, m, o);
        if (!lane) bc = m;
    }
    __syncthreads();
    float inv = 1.f / bc;
#pragma unroll
    for (int i = 0; i < 4; i++){
        float sv = e[i] * inv;
        g_soft[b*MM + tid + i*512] = sv;
        if (extra) extra[b*MM + tid + i*512] = sv;
    }
}

__global__ void k_upart(int k){
    __shared__ float red[8][EE];
    int chunk = blockIdx.x, b = blockIdx.y;
    int tid = threadIdx.x, w = tid >> 5, lane = tid & 31;
    int m0 = chunk*128 + w*16;
    const __half2* mg = (const __half2*)(g_mg + (size_t)k*BME + ((size_t)(b*MM + m0))*EE);
    const float* sp = g_soft + b*MM + m0;
    float a0=0.f, a1=0.f, a2=0.f, a3=0.f;
#pragma unroll 4
    for (int i = 0; i < 16; i++){
        float s = sp[i];
        uint2 rv = *(const uint2*)(mg + (size_t)i*64 + lane*2);
        float2 x0 = __half22float2(*(__half2*)&rv.x);
        float2 x1 = __half22float2(*(__half2*)&rv.y);
        a0 += s*x0.x; a1 += s*x0.y; a2 += s*x1.x; a3 += s*x1.y;
    }
    red[w][lane*4+0] = a0; red[w][lane*4+1] = a1;
    red[w][lane*4+2] = a2; red[w][lane*4+3] = a3;
    __syncthreads();
    if (tid < EE){
        float acc = 0.f;
#pragma unroll
        for (int i = 0; i < 8; i++) acc += red[i][tid];
        g_part[chunk][b*EE + tid] = acc;
    }
}

__global__ void k_ufinal(int uin, int uout){
    int b = blockIdx.x, e = threadIdx.x;
    float acc = g_u[uin][b*EE + e];
#pragma unroll
    for (int c = 0; c < 16; c++) acc += g_part[c][b*EE + e];
    g_u[uout][b*EE + e] = acc;
}

// ---------------- launch ----------------
extern "C" void kernel_launch(void* const* d_in, const int* in_sizes, int n_in,
                              void* d_out, int out_size){
    const int*   story    = (const int*)  d_in[0];
    const int*   kb_len   = (const int*)  d_in[1];
    const int*   conv_len = (const int*)  d_in[2];
    const float* dh       = (const float*)d_in[4];
    const float* tf       = (const float*)d_in[5];
    const float* q        = (const float*)d_in[6];
    const float* gp       = (const float*)d_in[7];
    const float* C        = (const float*)d_in[8];
    const float* wA1      = (const float*)d_in[9];
    const float* bA1      = (const float*)d_in[10];
    const float* wA2      = (const float*)d_in[11];
    const float* bA2      = (const float*)d_in[12];
    float* out = (float*)d_out;   // [0:BM) prob_soft, [BM:2BM) prob_logits

    cudaFuncSetAttribute(k_mlp, cudaFuncAttributeMaxDynamicSharedMemorySize, SMEMSZ);

    k_prepw <<<dim3(128,2), 128>>>(wA1, wA2);
    k_init  <<<BB, EE>>>(tf, wA1, bA1, q);
    k_mlp   <<<NCTA, 512, SMEMSZ>>>(story, kb_len, conv_len, dh, C, bA2, gp);

    // hop 0
    k_logits <<<1024, 256>>>(0, 0, nullptr);
    k_softmax<<<BB, 512>>>(nullptr);
    k_upart  <<<dim3(16, BB), 256>>>(1);
    k_ufinal <<<BB, EE>>>(0, 1);
    // hop 1
    k_logits <<<1024, 256>>>(1, 1, nullptr);
    k_softmax<<<BB, 512>>>(nullptr);
    k_upart  <<<dim3(16, BB), 256>>>(2);
    k_ufinal <<<BB, EE>>>(1, 0);
    // hop 2 (final outputs)
    k_logits <<<1024, 256>>>(2, 0, out + BM);
    k_softmax<<<BB, 512>>>(out);
}

// round 13
// speedup vs baseline: 1.2529x; 1.0116x over previous
#include <cuda_runtime.h>
#include <cuda_bf16.h>
#include <cuda_fp16.h>
#include <cstdint>

#define BB 16
#define MM 2048
#define SS 6
#define EE 128
#define LCC 512
#define VV 32000
#define BM (BB*MM)        // 32768
#define VE (VV*EE)
#define BME (BM*EE)
#define NTILES 1536       // 3 k * 512 tiles of 64 rows
#define NCTA 148

// ---------------- static device scratch ----------------
__device__ __half g_mg[3u*BME];     // MLP(bag)*gp, fp16, [k][g][e]
__device__ float g_tb[BB*EE];       // tf@wA1_bottom + bA1
__device__ float g_u[2][BB*EE];
__device__ float g_logits[BM];
__device__ float g_soft[BM];
__device__ float g_part[16][BB*EE];
__device__ uint4 g_wh[2][2048];     // W^T bf16-hi images, swizzled (32KB each)
__device__ uint4 g_wl[2][2048];     // bf16-lo images

// ---------------- helpers ----------------
__device__ __forceinline__ uint32_t smem_u32(const void* p){
    uint32_t a;
    asm("{ .reg .u64 t; cvta.to.shared.u64 t, %1; cvt.u32.u64 %0, t; }" : "=r"(a) : "l"(p));
    return a;
}
__device__ __forceinline__ uint32_t packbf(float hi, float lo){
    uint32_t r;
    asm("cvt.rn.bf16x2.f32 %0, %1, %2;" : "=r"(r) : "f"(hi), "f"(lo));
    return r;
}
// swizzled byte offset of bf16 (r, c) in an Nx128 tile (256B rows); keeps chunk bit 3.
__device__ __forceinline__ int swz(int r, int c){
    int ch = c >> 3;
    ch = (ch & 8) | ((ch ^ r) & 7);
    return r*256 + ch*16 + (c & 7)*2;
}
__device__ __forceinline__ void ldm4(uint32_t addr, uint32_t r[4]){
    asm volatile("ldmatrix.sync.aligned.m8n8.x4.shared.b16 {%0,%1,%2,%3}, [%4];"
        : "=r"(r[0]), "=r"(r[1]), "=r"(r[2]), "=r"(r[3]) : "r"(addr));
}
__device__ __forceinline__ void mma_bf16(float c[4], const uint32_t a[4], uint32_t b0, uint32_t b1){
    asm volatile("mma.sync.aligned.m16n8k16.row.col.f32.bf16.bf16.f32 "
        "{%0,%1,%2,%3}, {%4,%5,%6,%7}, {%8,%9}, {%0,%1,%2,%3};"
        : "+f"(c[0]), "+f"(c[1]), "+f"(c[2]), "+f"(c[3])
        : "r"(a[0]), "r"(a[1]), "r"(a[2]), "r"(a[3]), "r"(b0), "r"(b1));
}

// ---------------- mbarrier ----------------
#define MBAR_INIT(a, c) \
    asm volatile("mbarrier.init.shared.b64 [%0], %1;" :: "r"((uint32_t)(a)), "r"((uint32_t)(c)) : "memory")
#define MBAR_ARRIVE(a) \
    asm volatile("mbarrier.arrive.shared.b64 _, [%0];" :: "r"((uint32_t)(a)) : "memory")
#define MBAR_WAIT(mbar, par) do { \
    uint32_t _m = (uint32_t)(mbar), _p = (uint32_t)(par), _d; \
    asm volatile("{\n\t.reg .pred p;\n\t" \
        "mbarrier.try_wait.parity.acquire.cta.shared::cta.b64 p, [%1], %2;\n\t" \
        "selp.b32 %0, 1, 0, p;\n\t}" : "=r"(_d) : "r"(_m), "r"(_p) : "memory"); \
    if (!_d) { \
        asm volatile("{\n\t.reg .pred P1;\n\t" \
            "WL_%=:\n\t" \
            "mbarrier.try_wait.parity.acquire.cta.shared::cta.b64 P1, [%0], %1, 0x989680;\n\t" \
            "@P1 bra.uni WD_%=;\n\t" \
            "bra.uni WL_%=;\n\t" \
            "WD_%=:\n\t}" :: "r"(_m), "r"(_p) : "memory"); \
    } \
} while(0)

// ---------------- k_prepw: both layers' W^T bf16 hi/lo images ----------------
__global__ void k_prepw(const float* __restrict__ wA1, const float* __restrict__ wA2){
    int n = blockIdx.x, m = blockIdx.y, kk = threadIdx.x;
    const float* W = m ? wA2 : wA1;
    float w = W[kk*EE + n];
    float hf = __bfloat162float(__float2bfloat16(w));
    float lf = w - hf;
    float hn = __shfl_down_sync(0xffffffffu, hf, 1);
    float ln = __shfl_down_sync(0xffffffffu, lf, 1);
    if (!(kk & 1)){
        int off = swz(n, kk);
        *(uint32_t*)((char*)g_wh[m] + off) = packbf(hn, hf);
        *(uint32_t*)((char*)g_wl[m] + off) = packbf(ln, lf);
    }
}

// ---------------- k_init: tb + u0 ----------------
__global__ void k_init(const float* __restrict__ tf, const float* __restrict__ wA1,
                       const float* __restrict__ bA1, const float* __restrict__ q){
    int b = blockIdx.x, j = threadIdx.x;
    float acc = bA1[j];
#pragma unroll 8
    for (int e = 0; e < EE; e++)
        acc += tf[b*EE + e] * wA1[(EE + e)*EE + j];
    g_tb[b*EE + j] = acc;
    g_u[0][b*EE + j] = q[b*EE + j];
}

// ---------------- persistent warp-specialized MLP (unchanged) ----------------
#define SW1H 0
#define SW1L 32768
#define SW2H 65536
#define SW2L 98304
#define SA(s)   (131072 + (s)*32768)
#define SBAR    196608
#define SMEMSZ  196672

struct Frag { uint32_t ah[2][4], al[2][4], wh[2][4], wl[2][4]; };

__device__ __forceinline__ void frag_load(Frag& f, uint32_t sAh, uint32_t sAl,
        uint32_t sWh, uint32_t sWl, int wm, int wn, int rsel, int k0){
    ldm4(sAh + swz(wm*32 + rsel,      k0), f.ah[0]);
    ldm4(sAh + swz(wm*32 + 16 + rsel, k0), f.ah[1]);
    ldm4(sAl + swz(wm*32 + rsel,      k0), f.al[0]);
    ldm4(sAl + swz(wm*32 + 16 + rsel, k0), f.al[1]);
    ldm4(sWh + swz(wn*32 + rsel,      k0), f.wh[0]);
    ldm4(sWh + swz(wn*32 + 16 + rsel, k0), f.wh[1]);
    ldm4(sWl + swz(wn*32 + rsel,      k0), f.wl[0]);
    ldm4(sWl + swz(wn*32 + 16 + rsel, k0), f.wl[1]);
}

__device__ __forceinline__ void frag_mma(float acc[2][4][4], const Frag& f){
#pragma unroll
    for (int nt2 = 0; nt2 < 2; nt2++)
#pragma unroll
        for (int mt = 0; mt < 2; mt++){
            mma_bf16(acc[mt][nt2*2],   f.ah[mt], f.wh[nt2][0], f.wh[nt2][2]);
            mma_bf16(acc[mt][nt2*2+1], f.ah[mt], f.wh[nt2][1], f.wh[nt2][3]);
            mma_bf16(acc[mt][nt2*2],   f.ah[mt], f.wl[nt2][0], f.wl[nt2][2]);
            mma_bf16(acc[mt][nt2*2+1], f.ah[mt], f.wl[nt2][1], f.wl[nt2][3]);
            mma_bf16(acc[mt][nt2*2],   f.al[mt], f.wh[nt2][0], f.wh[nt2][2]);
            mma_bf16(acc[mt][nt2*2+1], f.al[mt], f.wh[nt2][1], f.wh[nt2][3]);
        }
}

__device__ __forceinline__ void gemm_fused(uint32_t sAh, uint32_t sAl,
                                           uint32_t sWh, uint32_t sWl,
                                           int wm, int wn, int rsel, int csel,
                                           float acc[2][4][4]){
    Frag f[2];
    frag_load(f[0], sAh, sAl, sWh, sWl, wm, wn, rsel, csel);
#pragma unroll
    for (int ks = 0; ks < 8; ks++){
        if (ks < 7)
            frag_load(f[(ks+1)&1], sAh, sAl, sWh, sWl, wm, wn, rsel, (ks+1)*16 + csel);
        frag_mma(acc, f[ks&1]);
    }
}

__global__ void __launch_bounds__(512, 1)
k_mlp(const int* __restrict__ story, const int* __restrict__ kb_len,
      const int* __restrict__ conv_len, const float* __restrict__ dh,
      const float* __restrict__ C, const float* __restrict__ bA2,
      const float* __restrict__ gp)
{
    extern __shared__ char smem[];
    const uint32_t sb = smem_u32(smem);
    const int tid = threadIdx.x, wid = tid >> 5, lane = tid & 31;
    const int bid = blockIdx.x;

    {
        uint4* s4 = (uint4*)smem;
        for (int i = tid; i < 2048; i += 512){
            s4[i]        = g_wh[0][i];
            s4[i+2048]   = g_wl[0][i];
            s4[i+4096]   = g_wh[1][i];
            s4[i+6144]   = g_wl[1][i];
        }
    }
    if (tid == 0){
        MBAR_INIT(sb + SBAR +  0, 256);   // full[0]
        MBAR_INIT(sb + SBAR +  8, 256);   // full[1]
        MBAR_INIT(sb + SBAR + 16, 256);   // empty[0]
        MBAR_INIT(sb + SBAR + 24, 256);   // empty[1]
    }
    __syncthreads();

    if (wid >= 8){
        // ---------- producer: 8 warps ----------
        const int ptid = tid - 256;
        int it = 0;
        for (int t = bid; t < NTILES; t += NCTA, it++){
            const int s = it & 1;
            const int k = t / 512, g0 = (t & 511) * 64, b = g0 >> 11;
            MBAR_WAIT(sb + SBAR + 16 + s*8, ((it>>1)&1)^1);
            const float* Ck = C + (size_t)k * VE;
            const int kb = __ldg(kb_len + b), cl = __ldg(conv_len + b);
            char* aH = smem + SA(s);
            char* aL = aH + 16384;
#pragma unroll 4
            for (int i = 0; i < 8; i++){
                int item = ptid + (i << 8);
                int r = item >> 5, cq = item & 31;
                int g = g0 + r, m = g & (MM-1);
                const int* st = story + (size_t)g * SS;
                float4 sacc = make_float4(0.f, 0.f, 0.f, 0.f);
#pragma unroll
                for (int j = 0; j < 6; j++){
                    float4 v = __ldg((const float4*)(Ck + (size_t)st[j]*EE) + cq);
                    sacc.x += v.x; sacc.y += v.y; sacc.z += v.z; sacc.w += v.w;
                }
                int idx = m - kb;
                if (idx >= 0 && idx < cl){
                    float4 dv = __ldg((const float4*)(dh + ((size_t)b*LCC + idx)*EE) + cq);
                    sacc.x += dv.x; sacc.y += dv.y; sacc.z += dv.z; sacc.w += dv.w;
                }
                float hx = __bfloat162float(__float2bfloat16(sacc.x));
                float hy = __bfloat162float(__float2bfloat16(sacc.y));
                float hz = __bfloat162float(__float2bfloat16(sacc.z));
                float hw = __bfloat162float(__float2bfloat16(sacc.w));
                int off = swz(r, cq*4);
                uint2 hv, lv;
                hv.x = packbf(hy, hx);           hv.y = packbf(hw, hz);
                lv.x = packbf(sacc.y - hy, sacc.x - hx);
                lv.y = packbf(sacc.w - hw, sacc.z - hz);
                *(uint2*)(aH + off) = hv;
                *(uint2*)(aL + off) = lv;
            }
            MBAR_ARRIVE(sb + SBAR + s*8);
        }
    } else {
        // ---------- consumer: 8 warps ----------
        const int wm = wid & 1, wn = wid >> 1;
        const int rsel = (lane & 7) + (lane & 8);
        const int csel = (lane & 16) >> 1;
        int it = 0;
        for (int t = bid; t < NTILES; t += NCTA, it++){
            const int s = it & 1;
            const int k = t / 512, g0 = (t & 511) * 64, b = g0 >> 11;
            const uint32_t sA = sb + SA(s), sAL = sA + 16384;
            MBAR_WAIT(sb + SBAR + s*8, (it>>1)&1);

            float acc[2][4][4];
#pragma unroll
            for (int mt=0; mt<2; mt++)
#pragma unroll
                for (int nt=0; nt<4; nt++)
#pragma unroll
                    for (int i=0; i<4; i++) acc[mt][nt][i] = 0.f;

            gemm_fused(sA, sAL, sb + SW1H, sb + SW1L, wm, wn, rsel, csel, acc);
            asm volatile("bar.sync 1, 256;" ::: "memory");

            // epilogue 1: +tb, lrelu, bf16-split -> overwrite A slot
#pragma unroll
            for (int nt = 0; nt < 4; nt++){
                int gc = wn*32 + nt*8 + (lane & 3)*2;
                float2 tb = *(const float2*)(g_tb + b*EE + gc);
#pragma unroll
                for (int mt = 0; mt < 2; mt++)
#pragma unroll
                    for (int h = 0; h < 2; h++){
                        int rl = wm*32 + mt*16 + (lane >> 2) + h*8;
                        float y0 = acc[mt][nt][h*2]   + tb.x;
                        float y1 = acc[mt][nt][h*2+1] + tb.y;
                        y0 = y0 > 0.f ? y0 : 0.1f*y0;
                        y1 = y1 > 0.f ? y1 : 0.1f*y1;
                        float h0 = __bfloat162float(__float2bfloat16(y0));
                        float h1 = __bfloat162float(__float2bfloat16(y1));
                        int off = swz(rl, gc);
                        *(uint32_t*)(smem + SA(s) + off)         = packbf(h1, h0);
                        *(uint32_t*)(smem + SA(s) + 16384 + off) = packbf(y1 - h1, y0 - h0);
                    }
            }
            asm volatile("bar.sync 1, 256;" ::: "memory");

#pragma unroll
            for (int mt=0; mt<2; mt++)
#pragma unroll
                for (int nt=0; nt<4; nt++)
#pragma unroll
                    for (int i=0; i<4; i++) acc[mt][nt][i] = 0.f;

            gemm_fused(sA, sAL, sb + SW2H, sb + SW2L, wm, wn, rsel, csel, acc);
            MBAR_ARRIVE(sb + SBAR + 16 + s*8);

            // epilogue 2: +bA2, *gp -> g_mg (fp16)
#pragma unroll
            for (int mt = 0; mt < 2; mt++)
#pragma unroll
                for (int h = 0; h < 2; h++){
                    int rl = wm*32 + mt*16 + (lane >> 2) + h*8;
                    float gv = __ldg(gp + g0 + rl);
                    __half* op = g_mg + (size_t)k*BME + (size_t)(g0 + rl)*EE;
#pragma unroll
                    for (int nt = 0; nt < 4; nt++){
                        int gc = wn*32 + nt*8 + (lane & 3)*2;
                        float2 bv = *(const float2*)(bA2 + gc);
                        float ox = (acc[mt][nt][h*2]   + bv.x) * gv;
                        float oy = (acc[mt][nt][h*2+1] + bv.y) * gv;
                        *(__half2*)(op + gc) = __floats2half2_rn(ox, oy);
                    }
                }
        }
    }
}

// ---------------- phase 2 ----------------
// v2: half-warp per row, uint4 loads (4x16B in flight per thread), 8 rows/warp
__global__ void k_logits(int k, int usel, float* __restrict__ extra){
    int gw = (blockIdx.x * blockDim.x + threadIdx.x) >> 5;
    int lane = threadIdx.x & 31;
    int sub = lane & 15, half = lane >> 4;
    int g0 = gw * 8;
    int b = g0 >> 11;
    float4 ua = *(const float4*)(g_u[usel] + b*EE + sub*8);
    float4 ub = *(const float4*)(g_u[usel] + b*EE + sub*8 + 4);
    const __half* mg = g_mg + (size_t)k*BME + (size_t)g0*EE;
    float p[4];
#pragma unroll
    for (int i = 0; i < 4; i++){
        int row = i*2 + half;
        uint4 rv = *(const uint4*)(mg + (size_t)row*EE + sub*8);
        float2 x0 = __half22float2(*(__half2*)&rv.x);
        float2 x1 = __half22float2(*(__half2*)&rv.y);
        float2 x2 = __half22float2(*(__half2*)&rv.z);
        float2 x3 = __half22float2(*(__half2*)&rv.w);
        p[i] = x0.x*ua.x + x0.y*ua.y + x1.x*ua.z + x1.y*ua.w
             + x2.x*ub.x + x2.y*ub.y + x3.x*ub.z + x3.y*ub.w;
    }
#pragma unroll
    for (int i = 0; i < 4; i++)
#pragma unroll
        for (int o = 8; o; o >>= 1) p[i] += __shfl_xor_sync(0xffffffffu, p[i], o);
    if (!sub){
#pragma unroll
        for (int i = 0; i < 4; i++){
            int row = g0 + i*2 + half;
            g_logits[row] = p[i];
            if (extra) extra[row] = p[i];
        }
    }
}

// warp-shuffle softmax
__global__ void k_softmax(float* __restrict__ extra){
    __shared__ float wred[16];
    __shared__ float bc;
    int b = blockIdx.x, tid = threadIdx.x, w = tid >> 5, lane = tid & 31;
    const float* l = g_logits + b*MM;
    float v[4];
#pragma unroll
    for (int i = 0; i < 4; i++) v[i] = l[tid + i*512];
    float mx = fmaxf(fmaxf(v[0], v[1]), fmaxf(v[2], v[3]));
#pragma unroll
    for (int o = 16; o; o >>= 1) mx = fmaxf(mx, __shfl_xor_sync(0xffffffffu, mx, o));
    if (!lane) wred[w] = mx;
    __syncthreads();
    if (tid < 32){
        float m = (lane < 16) ? wred[lane] : -3.4e38f;
#pragma unroll
        for (int o = 8; o; o >>= 1) m = fmaxf(m, __shfl_xor_sync(0xffffffffu, m, o));
        if (!lane) bc = m;
    }
    __syncthreads();
    mx = bc;
    float e[4], ss = 0.f;
#pragma unroll
    for (int i = 0; i < 4; i++){ e[i] = expf(v[i] - mx); ss += e[i]; }
#pragma unroll
    for (int o = 16; o; o >>= 1) ss += __shfl_xor_sync(0xffffffffu, ss, o);
    if (!lane) wred[w] = ss;
    __syncthreads();
    if (tid < 32){
        float m = (lane < 16) ? wred[lane] : 0.f;
#pragma unroll
        for (int o = 8; o; o >>= 1) m += __shfl_xor_sync(0xffffffffu, m, o);
        if (!lane) bc = m;
    }
    __syncthreads();
    float inv = 1.f / bc;
#pragma unroll
    for (int i = 0; i < 4; i++){
        float sv = e[i] * inv;
        g_soft[b*MM + tid + i*512] = sv;
        if (extra) extra[b*MM + tid + i*512] = sv;
    }
}

// v2: half-warp per row, uint4 loads (8x16B in flight), 16 rows/warp
__global__ void k_upart(int k){
    __shared__ float red[8][EE];
    int chunk = blockIdx.x, b = blockIdx.y;
    int tid = threadIdx.x, w = tid >> 5, lane = tid & 31;
    int sub = lane & 15, half = lane >> 4;
    int m0 = chunk*128 + w*16;
    const __half* mg = g_mg + (size_t)k*BME + ((size_t)(b*MM + m0))*EE;
    const float* sp = g_soft + b*MM + m0;
    float a[8] = {0.f,0.f,0.f,0.f,0.f,0.f,0.f,0.f};
#pragma unroll
    for (int i = 0; i < 8; i++){
        int row = i*2 + half;
        float s = sp[row];
        uint4 rv = *(const uint4*)(mg + (size_t)row*EE + sub*8);
        float2 x0 = __half22float2(*(__half2*)&rv.x);
        float2 x1 = __half22float2(*(__half2*)&rv.y);
        float2 x2 = __half22float2(*(__half2*)&rv.z);
        float2 x3 = __half22float2(*(__half2*)&rv.w);
        a[0] += s*x0.x; a[1] += s*x0.y; a[2] += s*x1.x; a[3] += s*x1.y;
        a[4] += s*x2.x; a[5] += s*x2.y; a[6] += s*x3.x; a[7] += s*x3.y;
    }
#pragma unroll
    for (int j = 0; j < 8; j++) a[j] += __shfl_xor_sync(0xffffffffu, a[j], 16);
    if (!half){
#pragma unroll
        for (int j = 0; j < 8; j++) red[w][sub*8 + j] = a[j];
    }
    __syncthreads();
    if (tid < EE){
        float acc = 0.f;
#pragma unroll
        for (int i = 0; i < 8; i++) acc += red[i][tid];
        g_part[chunk][b*EE + tid] = acc;
    }
}

__global__ void k_ufinal(int uin, int uout){
    int b = blockIdx.x, e = threadIdx.x;
    float acc = g_u[uin][b*EE + e];
#pragma unroll
    for (int c = 0; c < 16; c++) acc += g_part[c][b*EE + e];
    g_u[uout][b*EE + e] = acc;
}

// ---------------- launch ----------------
extern "C" void kernel_launch(void* const* d_in, const int* in_sizes, int n_in,
                              void* d_out, int out_size){
    const int*   story    = (const int*)  d_in[0];
    const int*   kb_len   = (const int*)  d_in[1];
    const int*   conv_len = (const int*)  d_in[2];
    const float* dh       = (const float*)d_in[4];
    const float* tf       = (const float*)d_in[5];
    const float* q        = (const float*)d_in[6];
    const float* gp       = (const float*)d_in[7];
    const float* C        = (const float*)d_in[8];
    const float* wA1      = (const float*)d_in[9];
    const float* bA1      = (const float*)d_in[10];
    const float* wA2      = (const float*)d_in[11];
    const float* bA2      = (const float*)d_in[12];
    float* out = (float*)d_out;   // [0:BM) prob_soft, [BM:2BM) prob_logits

    cudaFuncSetAttribute(k_mlp, cudaFuncAttributeMaxDynamicSharedMemorySize, SMEMSZ);

    k_prepw <<<dim3(128,2), 128>>>(wA1, wA2);
    k_init  <<<BB, EE>>>(tf, wA1, bA1, q);
    k_mlp   <<<NCTA, 512, SMEMSZ>>>(story, kb_len, conv_len, dh, C, bA2, gp);

    // hop 0
    k_logits <<<512, 256>>>(0, 0, nullptr);
    k_softmax<<<BB, 512>>>(nullptr);
    k_upart  <<<dim3(16, BB), 256>>>(1);
    k_ufinal <<<BB, EE>>>(0, 1);
    // hop 1
    k_logits <<<512, 256>>>(1, 1, nullptr);
    k_softmax<<<BB, 512>>>(nullptr);
    k_upart  <<<dim3(16, BB), 256>>>(2);
    k_ufinal <<<BB, EE>>>(1, 0);
    // hop 2 (final outputs)
    k_logits <<<512, 256>>>(2, 0, out + BM);
    k_softmax<<<BB, 512>>>(out);
}

// round 14
// speedup vs baseline: 1.2789x; 1.0207x over previous
#include <cuda_runtime.h>
#include <cuda_bf16.h>
#include <cuda_fp16.h>
#include <cstdint>

#define BB 16
#define MM 2048
#define SS 6
#define EE 128
#define LCC 512
#define VV 32000
#define BM (BB*MM)        // 32768
#define VE (VV*EE)
#define BME (BM*EE)
#define NTILES 1536       // 3 k * 512 tiles of 64 rows
#define NCTA 148

// ---------------- static device scratch ----------------
__device__ __half g_mg[3u*BME];     // MLP(bag)*gp, fp16, [k][g][e]
__device__ float g_tb[BB*EE];       // tf@wA1_bottom + bA1
__device__ float g_u[2][BB*EE];
__device__ float g_logits[BM];
__device__ float g_soft[BM];
__device__ float g_part[16][BB*EE];
__device__ uint4 g_wh[2][2048];     // W^T bf16-hi images, swizzled (32KB each)
__device__ uint4 g_wl[2][2048];     // bf16-lo images

// ---------------- helpers ----------------
__device__ __forceinline__ uint32_t smem_u32(const void* p){
    uint32_t a;
    asm("{ .reg .u64 t; cvta.to.shared.u64 t, %1; cvt.u32.u64 %0, t; }" : "=r"(a) : "l"(p));
    return a;
}
__device__ __forceinline__ uint32_t packbf(float hi, float lo){
    uint32_t r;
    asm("cvt.rn.bf16x2.f32 %0, %1, %2;" : "=r"(r) : "f"(hi), "f"(lo));
    return r;
}
// swizzled byte offset of bf16 (r, c) in an Nx128 tile (256B rows); keeps chunk bit 3.
__device__ __forceinline__ int swz(int r, int c){
    int ch = c >> 3;
    ch = (ch & 8) | ((ch ^ r) & 7);
    return r*256 + ch*16 + (c & 7)*2;
}
__device__ __forceinline__ void ldm4(uint32_t addr, uint32_t r[4]){
    asm volatile("ldmatrix.sync.aligned.m8n8.x4.shared.b16 {%0,%1,%2,%3}, [%4];"
        : "=r"(r[0]), "=r"(r[1]), "=r"(r[2]), "=r"(r[3]) : "r"(addr));
}
__device__ __forceinline__ void mma_bf16(float c[4], const uint32_t a[4], uint32_t b0, uint32_t b1){
    asm volatile("mma.sync.aligned.m16n8k16.row.col.f32.bf16.bf16.f32 "
        "{%0,%1,%2,%3}, {%4,%5,%6,%7}, {%8,%9}, {%0,%1,%2,%3};"
        : "+f"(c[0]), "+f"(c[1]), "+f"(c[2]), "+f"(c[3])
        : "r"(a[0]), "r"(a[1]), "r"(a[2]), "r"(a[3]), "r"(b0), "r"(b1));
}

// ---------------- mbarrier ----------------
#define MBAR_INIT(a, c) \
    asm volatile("mbarrier.init.shared.b64 [%0], %1;" :: "r"((uint32_t)(a)), "r"((uint32_t)(c)) : "memory")
#define MBAR_ARRIVE(a) \
    asm volatile("mbarrier.arrive.shared.b64 _, [%0];" :: "r"((uint32_t)(a)) : "memory")
#define MBAR_WAIT(mbar, par) do { \
    uint32_t _m = (uint32_t)(mbar), _p = (uint32_t)(par), _d; \
    asm volatile("{\n\t.reg .pred p;\n\t" \
        "mbarrier.try_wait.parity.acquire.cta.shared::cta.b64 p, [%1], %2;\n\t" \
        "selp.b32 %0, 1, 0, p;\n\t}" : "=r"(_d) : "r"(_m), "r"(_p) : "memory"); \
    if (!_d) { \
        asm volatile("{\n\t.reg .pred P1;\n\t" \
            "WL_%=:\n\t" \
            "mbarrier.try_wait.parity.acquire.cta.shared::cta.b64 P1, [%0], %1, 0x989680;\n\t" \
            "@P1 bra.uni WD_%=;\n\t" \
            "bra.uni WL_%=;\n\t" \
            "WD_%=:\n\t}" :: "r"(_m), "r"(_p) : "memory"); \
    } \
} while(0)

// ---------------- k_prepw: both layers' W^T bf16 hi/lo images ----------------
__global__ void k_prepw(const float* __restrict__ wA1, const float* __restrict__ wA2){
    int n = blockIdx.x, m = blockIdx.y, kk = threadIdx.x;
    const float* W = m ? wA2 : wA1;
    float w = W[kk*EE + n];
    float hf = __bfloat162float(__float2bfloat16(w));
    float lf = w - hf;
    float hn = __shfl_down_sync(0xffffffffu, hf, 1);
    float ln = __shfl_down_sync(0xffffffffu, lf, 1);
    if (!(kk & 1)){
        int off = swz(n, kk);
        *(uint32_t*)((char*)g_wh[m] + off) = packbf(hn, hf);
        *(uint32_t*)((char*)g_wl[m] + off) = packbf(ln, lf);
    }
}

// ---------------- k_init: tb + u0 ----------------
__global__ void k_init(const float* __restrict__ tf, const float* __restrict__ wA1,
                       const float* __restrict__ bA1, const float* __restrict__ q){
    int b = blockIdx.x, j = threadIdx.x;
    float acc = bA1[j];
#pragma unroll 8
    for (int e = 0; e < EE; e++)
        acc += tf[b*EE + e] * wA1[(EE + e)*EE + j];
    g_tb[b*EE + j] = acc;
    g_u[0][b*EE + j] = q[b*EE + j];
}

// ---------------- persistent warp-specialized MLP (unchanged) ----------------
#define SW1H 0
#define SW1L 32768
#define SW2H 65536
#define SW2L 98304
#define SA(s)   (131072 + (s)*32768)
#define SBAR    196608
#define SMEMSZ  196672

struct Frag { uint32_t ah[2][4], al[2][4], wh[2][4], wl[2][4]; };

__device__ __forceinline__ void frag_load(Frag& f, uint32_t sAh, uint32_t sAl,
        uint32_t sWh, uint32_t sWl, int wm, int wn, int rsel, int k0){
    ldm4(sAh + swz(wm*32 + rsel,      k0), f.ah[0]);
    ldm4(sAh + swz(wm*32 + 16 + rsel, k0), f.ah[1]);
    ldm4(sAl + swz(wm*32 + rsel,      k0), f.al[0]);
    ldm4(sAl + swz(wm*32 + 16 + rsel, k0), f.al[1]);
    ldm4(sWh + swz(wn*32 + rsel,      k0), f.wh[0]);
    ldm4(sWh + swz(wn*32 + 16 + rsel, k0), f.wh[1]);
    ldm4(sWl + swz(wn*32 + rsel,      k0), f.wl[0]);
    ldm4(sWl + swz(wn*32 + 16 + rsel, k0), f.wl[1]);
}

__device__ __forceinline__ void frag_mma(float acc[2][4][4], const Frag& f){
#pragma unroll
    for (int nt2 = 0; nt2 < 2; nt2++)
#pragma unroll
        for (int mt = 0; mt < 2; mt++){
            mma_bf16(acc[mt][nt2*2],   f.ah[mt], f.wh[nt2][0], f.wh[nt2][2]);
            mma_bf16(acc[mt][nt2*2+1], f.ah[mt], f.wh[nt2][1], f.wh[nt2][3]);
            mma_bf16(acc[mt][nt2*2],   f.ah[mt], f.wl[nt2][0], f.wl[nt2][2]);
            mma_bf16(acc[mt][nt2*2+1], f.ah[mt], f.wl[nt2][1], f.wl[nt2][3]);
            mma_bf16(acc[mt][nt2*2],   f.al[mt], f.wh[nt2][0], f.wh[nt2][2]);
            mma_bf16(acc[mt][nt2*2+1], f.al[mt], f.wh[nt2][1], f.wh[nt2][3]);
        }
}

__device__ __forceinline__ void gemm_fused(uint32_t sAh, uint32_t sAl,
                                           uint32_t sWh, uint32_t sWl,
                                           int wm, int wn, int rsel, int csel,
                                           float acc[2][4][4]){
    Frag f[2];
    frag_load(f[0], sAh, sAl, sWh, sWl, wm, wn, rsel, csel);
#pragma unroll
    for (int ks = 0; ks < 8; ks++){
        if (ks < 7)
            frag_load(f[(ks+1)&1], sAh, sAl, sWh, sWl, wm, wn, rsel, (ks+1)*16 + csel);
        frag_mma(acc, f[ks&1]);
    }
}

__global__ void __launch_bounds__(512, 1)
k_mlp(const int* __restrict__ story, const int* __restrict__ kb_len,
      const int* __restrict__ conv_len, const float* __restrict__ dh,
      const float* __restrict__ C, const float* __restrict__ bA2,
      const float* __restrict__ gp)
{
    extern __shared__ char smem[];
    const uint32_t sb = smem_u32(smem);
    const int tid = threadIdx.x, wid = tid >> 5, lane = tid & 31;
    const int bid = blockIdx.x;

    {
        uint4* s4 = (uint4*)smem;
        for (int i = tid; i < 2048; i += 512){
            s4[i]        = g_wh[0][i];
            s4[i+2048]   = g_wl[0][i];
            s4[i+4096]   = g_wh[1][i];
            s4[i+6144]   = g_wl[1][i];
        }
    }
    if (tid == 0){
        MBAR_INIT(sb + SBAR +  0, 256);   // full[0]
        MBAR_INIT(sb + SBAR +  8, 256);   // full[1]
        MBAR_INIT(sb + SBAR + 16, 256);   // empty[0]
        MBAR_INIT(sb + SBAR + 24, 256);   // empty[1]
    }
    __syncthreads();

    if (wid >= 8){
        // ---------- producer: 8 warps ----------
        const int ptid = tid - 256;
        int it = 0;
        for (int t = bid; t < NTILES; t += NCTA, it++){
            const int s = it & 1;
            const int k = t / 512, g0 = (t & 511) * 64, b = g0 >> 11;
            MBAR_WAIT(sb + SBAR + 16 + s*8, ((it>>1)&1)^1);
            const float* Ck = C + (size_t)k * VE;
            const int kb = __ldg(kb_len + b), cl = __ldg(conv_len + b);
            char* aH = smem + SA(s);
            char* aL = aH + 16384;
#pragma unroll 4
            for (int i = 0; i < 8; i++){
                int item = ptid + (i << 8);
                int r = item >> 5, cq = item & 31;
                int g = g0 + r, m = g & (MM-1);
                const int* st = story + (size_t)g * SS;
                float4 sacc = make_float4(0.f, 0.f, 0.f, 0.f);
#pragma unroll
                for (int j = 0; j < 6; j++){
                    float4 v = __ldg((const float4*)(Ck + (size_t)st[j]*EE) + cq);
                    sacc.x += v.x; sacc.y += v.y; sacc.z += v.z; sacc.w += v.w;
                }
                int idx = m - kb;
                if (idx >= 0 && idx < cl){
                    float4 dv = __ldg((const float4*)(dh + ((size_t)b*LCC + idx)*EE) + cq);
                    sacc.x += dv.x; sacc.y += dv.y; sacc.z += dv.z; sacc.w += dv.w;
                }
                float hx = __bfloat162float(__float2bfloat16(sacc.x));
                float hy = __bfloat162float(__float2bfloat16(sacc.y));
                float hz = __bfloat162float(__float2bfloat16(sacc.z));
                float hw = __bfloat162float(__float2bfloat16(sacc.w));
                int off = swz(r, cq*4);
                uint2 hv, lv;
                hv.x = packbf(hy, hx);           hv.y = packbf(hw, hz);
                lv.x = packbf(sacc.y - hy, sacc.x - hx);
                lv.y = packbf(sacc.w - hw, sacc.z - hz);
                *(uint2*)(aH + off) = hv;
                *(uint2*)(aL + off) = lv;
            }
            MBAR_ARRIVE(sb + SBAR + s*8);
        }
    } else {
        // ---------- consumer: 8 warps ----------
        const int wm = wid & 1, wn = wid >> 1;
        const int rsel = (lane & 7) + (lane & 8);
        const int csel = (lane & 16) >> 1;
        int it = 0;
        for (int t = bid; t < NTILES; t += NCTA, it++){
            const int s = it & 1;
            const int k = t / 512, g0 = (t & 511) * 64, b = g0 >> 11;
            const uint32_t sA = sb + SA(s), sAL = sA + 16384;
            MBAR_WAIT(sb + SBAR + s*8, (it>>1)&1);

            float acc[2][4][4];
#pragma unroll
            for (int mt=0; mt<2; mt++)
#pragma unroll
                for (int nt=0; nt<4; nt++)
#pragma unroll
                    for (int i=0; i<4; i++) acc[mt][nt][i] = 0.f;

            gemm_fused(sA, sAL, sb + SW1H, sb + SW1L, wm, wn, rsel, csel, acc);
            asm volatile("bar.sync 1, 256;" ::: "memory");

            // epilogue 1: +tb, lrelu, bf16-split -> overwrite A slot
#pragma unroll
            for (int nt = 0; nt < 4; nt++){
                int gc = wn*32 + nt*8 + (lane & 3)*2;
                float2 tb = *(const float2*)(g_tb + b*EE + gc);
#pragma unroll
                for (int mt = 0; mt < 2; mt++)
#pragma unroll
                    for (int h = 0; h < 2; h++){
                        int rl = wm*32 + mt*16 + (lane >> 2) + h*8;
                        float y0 = acc[mt][nt][h*2]   + tb.x;
                        float y1 = acc[mt][nt][h*2+1] + tb.y;
                        y0 = y0 > 0.f ? y0 : 0.1f*y0;
                        y1 = y1 > 0.f ? y1 : 0.1f*y1;
                        float h0 = __bfloat162float(__float2bfloat16(y0));
                        float h1 = __bfloat162float(__float2bfloat16(y1));
                        int off = swz(rl, gc);
                        *(uint32_t*)(smem + SA(s) + off)         = packbf(h1, h0);
                        *(uint32_t*)(smem + SA(s) + 16384 + off) = packbf(y1 - h1, y0 - h0);
                    }
            }
            asm volatile("bar.sync 1, 256;" ::: "memory");

#pragma unroll
            for (int mt=0; mt<2; mt++)
#pragma unroll
                for (int nt=0; nt<4; nt++)
#pragma unroll
                    for (int i=0; i<4; i++) acc[mt][nt][i] = 0.f;

            gemm_fused(sA, sAL, sb + SW2H, sb + SW2L, wm, wn, rsel, csel, acc);
            MBAR_ARRIVE(sb + SBAR + 16 + s*8);

            // epilogue 2: +bA2, *gp -> g_mg (fp16)
#pragma unroll
            for (int mt = 0; mt < 2; mt++)
#pragma unroll
                for (int h = 0; h < 2; h++){
                    int rl = wm*32 + mt*16 + (lane >> 2) + h*8;
                    float gv = __ldg(gp + g0 + rl);
                    __half* op = g_mg + (size_t)k*BME + (size_t)(g0 + rl)*EE;
#pragma unroll
                    for (int nt = 0; nt < 4; nt++){
                        int gc = wn*32 + nt*8 + (lane & 3)*2;
                        float2 bv = *(const float2*)(bA2 + gc);
                        float ox = (acc[mt][nt][h*2]   + bv.x) * gv;
                        float oy = (acc[mt][nt][h*2+1] + bv.y) * gv;
                        *(__half2*)(op + gc) = __floats2half2_rn(ox, oy);
                    }
                }
        }
    }
}

// ---------------- phase 2 ----------------
// v3: 16 rows/warp, half-warp per row, 8 batched uint4 loads per thread (2KB/warp in flight)
__global__ void k_logits(int k, int usel, float* __restrict__ extra){
    int gw = (blockIdx.x * blockDim.x + threadIdx.x) >> 5;
    int lane = threadIdx.x & 31;
    int sub = lane & 15, half = lane >> 4;
    int g0 = gw * 16;
    int b = g0 >> 11;
    float4 ua = *(const float4*)(g_u[usel] + b*EE + sub*8);
    float4 ub = *(const float4*)(g_u[usel] + b*EE + sub*8 + 4);
    const __half* mg = g_mg + (size_t)k*BME + (size_t)g0*EE;

    uint4 rv[8];
#pragma unroll
    for (int i = 0; i < 8; i++){
        int row = i*2 + half;
        rv[i] = *(const uint4*)(mg + (size_t)row*EE + sub*8);
    }
    float p[8];
#pragma unroll
    for (int i = 0; i < 8; i++){
        float2 x0 = __half22float2(*(__half2*)&rv[i].x);
        float2 x1 = __half22float2(*(__half2*)&rv[i].y);
        float2 x2 = __half22float2(*(__half2*)&rv[i].z);
        float2 x3 = __half22float2(*(__half2*)&rv[i].w);
        p[i] = x0.x*ua.x + x0.y*ua.y + x1.x*ua.z + x1.y*ua.w
             + x2.x*ub.x + x2.y*ub.y + x3.x*ub.z + x3.y*ub.w;
    }
#pragma unroll
    for (int i = 0; i < 8; i++)
#pragma unroll
        for (int o = 8; o; o >>= 1) p[i] += __shfl_xor_sync(0xffffffffu, p[i], o);
    if (!sub){
#pragma unroll
        for (int i = 0; i < 8; i++){
            int row = g0 + i*2 + half;
            g_logits[row] = p[i];
            if (extra) extra[row] = p[i];
        }
    }
}

// warp-shuffle softmax
__global__ void k_softmax(float* __restrict__ extra){
    __shared__ float wred[16];
    __shared__ float bc;
    int b = blockIdx.x, tid = threadIdx.x, w = tid >> 5, lane = tid & 31;
    const float* l = g_logits + b*MM;
    float v[4];
#pragma unroll
    for (int i = 0; i < 4; i++) v[i] = l[tid + i*512];
    float mx = fmaxf(fmaxf(v[0], v[1]), fmaxf(v[2], v[3]));
#pragma unroll
    for (int o = 16; o; o >>= 1) mx = fmaxf(mx, __shfl_xor_sync(0xffffffffu, mx, o));
    if (!lane) wred[w] = mx;
    __syncthreads();
    if (tid < 32){
        float m = (lane < 16) ? wred[lane] : -3.4e38f;
#pragma unroll
        for (int o = 8; o; o >>= 1) m = fmaxf(m, __shfl_xor_sync(0xffffffffu, m, o));
        if (!lane) bc = m;
    }
    __syncthreads();
    mx = bc;
    float e[4], ss = 0.f;
#pragma unroll
    for (int i = 0; i < 4; i++){ e[i] = expf(v[i] - mx); ss += e[i]; }
#pragma unroll
    for (int o = 16; o; o >>= 1) ss += __shfl_xor_sync(0xffffffffu, ss, o);
    if (!lane) wred[w] = ss;
    __syncthreads();
    if (tid < 32){
        float m = (lane < 16) ? wred[lane] : 0.f;
#pragma unroll
        for (int o = 8; o; o >>= 1) m += __shfl_xor_sync(0xffffffffu, m, o);
        if (!lane) bc = m;
    }
    __syncthreads();
    float inv = 1.f / bc;
#pragma unroll
    for (int i = 0; i < 4; i++){
        float sv = e[i] * inv;
        g_soft[b*MM + tid + i*512] = sv;
        if (extra) extra[b*MM + tid + i*512] = sv;
    }
}

// half-warp per row, uint4 loads (8x16B in flight), 16 rows/warp
__global__ void k_upart(int k){
    __shared__ float red[8][EE];
    int chunk = blockIdx.x, b = blockIdx.y;
    int tid = threadIdx.x, w = tid >> 5, lane = tid & 31;
    int sub = lane & 15, half = lane >> 4;
    int m0 = chunk*128 + w*16;
    const __half* mg = g_mg + (size_t)k*BME + ((size_t)(b*MM + m0))*EE;
    const float* sp = g_soft + b*MM + m0;
    float a[8] = {0.f,0.f,0.f,0.f,0.f,0.f,0.f,0.f};
#pragma unroll
    for (int i = 0; i < 8; i++){
        int row = i*2 + half;
        float s = sp[row];
        uint4 rv = *(const uint4*)(mg + (size_t)row*EE + sub*8);
        float2 x0 = __half22float2(*(__half2*)&rv.x);
        float2 x1 = __half22float2(*(__half2*)&rv.y);
        float2 x2 = __half22float2(*(__half2*)&rv.z);
        float2 x3 = __half22float2(*(__half2*)&rv.w);
        a[0] += s*x0.x; a[1] += s*x0.y; a[2] += s*x1.x; a[3] += s*x1.y;
        a[4] += s*x2.x; a[5] += s*x2.y; a[6] += s*x3.x; a[7] += s*x3.y;
    }
#pragma unroll
    for (int j = 0; j < 8; j++) a[j] += __shfl_xor_sync(0xffffffffu, a[j], 16);
    if (!half){
#pragma unroll
        for (int j = 0; j < 8; j++) red[w][sub*8 + j] = a[j];
    }
    __syncthreads();
    if (tid < EE){
        float acc = 0.f;
#pragma unroll
        for (int i = 0; i < 8; i++) acc += red[i][tid];
        g_part[chunk][b*EE + tid] = acc;
    }
}

__global__ void k_ufinal(int uin, int uout){
    int b = blockIdx.x, e = threadIdx.x;
    float acc = g_u[uin][b*EE + e];
#pragma unroll
    for (int c = 0; c < 16; c++) acc += g_part[c][b*EE + e];
    g_u[uout][b*EE + e] = acc;
}

// ---------------- launch ----------------
extern "C" void kernel_launch(void* const* d_in, const int* in_sizes, int n_in,
                              void* d_out, int out_size){
    const int*   story    = (const int*)  d_in[0];
    const int*   kb_len   = (const int*)  d_in[1];
    const int*   conv_len = (const int*)  d_in[2];
    const float* dh       = (const float*)d_in[4];
    const float* tf       = (const float*)d_in[5];
    const float* q        = (const float*)d_in[6];
    const float* gp       = (const float*)d_in[7];
    const float* C        = (const float*)d_in[8];
    const float* wA1      = (const float*)d_in[9];
    const float* bA1      = (const float*)d_in[10];
    const float* wA2      = (const float*)d_in[11];
    const float* bA2      = (const float*)d_in[12];
    float* out = (float*)d_out;   // [0:BM) prob_soft, [BM:2BM) prob_logits

    cudaFuncSetAttribute(k_mlp, cudaFuncAttributeMaxDynamicSharedMemorySize, SMEMSZ);

    k_prepw <<<dim3(128,2), 128>>>(wA1, wA2);
    k_init  <<<BB, EE>>>(tf, wA1, bA1, q);
    k_mlp   <<<NCTA, 512, SMEMSZ>>>(story, kb_len, conv_len, dh, C, bA2, gp);

    // hop 0
    k_logits <<<256, 256>>>(0, 0, nullptr);
    k_softmax<<<BB, 512>>>(nullptr);
    k_upart  <<<dim3(16, BB), 256>>>(1);
    k_ufinal <<<BB, EE>>>(0, 1);
    // hop 1
    k_logits <<<256, 256>>>(1, 1, nullptr);
    k_softmax<<<BB, 512>>>(nullptr);
    k_upart  <<<dim3(16, BB), 256>>>(2);
    k_ufinal <<<BB, EE>>>(1, 0);
    // hop 2 (final outputs)
    k_logits <<<256, 256>>>(2, 0, out + BM);
    k_softmax<<<BB, 512>>>(out);
}

// round 15
// speedup vs baseline: 1.3247x; 1.0358x over previous
#include <cuda_runtime.h>
#include <cuda_bf16.h>
#include <cuda_fp16.h>
#include <cstdint>

#define BB 16
#define MM 2048
#define SS 6
#define EE 128
#define LCC 512
#define VV 32000
#define BM (BB*MM)        // 32768
#define VE (VV*EE)
#define BME (BM*EE)
#define NTILES 1536       // 3 k * 512 tiles of 64 rows
#define NCTA 148

// ---------------- static device scratch ----------------
__device__ __half g_mg[3u*BME];     // MLP(bag)*gp, fp16, [k][g][e] (k=0 never stored)
__device__ float g_tb[BB*EE];       // tf@wA1_bottom + bA1
__device__ float g_u0[BB*EE];       // u0 = q
__device__ float g_logits[BM];
__device__ float g_soft[BM];
__device__ float g_part[2][16][BB*EE];
__device__ uint4 g_wh[2][2048];     // W^T bf16-hi images, swizzled (32KB each)
__device__ uint4 g_wl[2][2048];     // bf16-lo images

// ---------------- helpers ----------------
__device__ __forceinline__ uint32_t smem_u32(const void* p){
    uint32_t a;
    asm("{ .reg .u64 t; cvta.to.shared.u64 t, %1; cvt.u32.u64 %0, t; }" : "=r"(a) : "l"(p));
    return a;
}
__device__ __forceinline__ uint32_t packbf(float hi, float lo){
    uint32_t r;
    asm("cvt.rn.bf16x2.f32 %0, %1, %2;" : "=r"(r) : "f"(hi), "f"(lo));
    return r;
}
// swizzled byte offset of bf16 (r, c) in an Nx128 tile (256B rows); keeps chunk bit 3.
__device__ __forceinline__ int swz(int r, int c){
    int ch = c >> 3;
    ch = (ch & 8) | ((ch ^ r) & 7);
    return r*256 + ch*16 + (c & 7)*2;
}
__device__ __forceinline__ void ldm4(uint32_t addr, uint32_t r[4]){
    asm volatile("ldmatrix.sync.aligned.m8n8.x4.shared.b16 {%0,%1,%2,%3}, [%4];"
        : "=r"(r[0]), "=r"(r[1]), "=r"(r[2]), "=r"(r[3]) : "r"(addr));
}
__device__ __forceinline__ void mma_bf16(float c[4], const uint32_t a[4], uint32_t b0, uint32_t b1){
    asm volatile("mma.sync.aligned.m16n8k16.row.col.f32.bf16.bf16.f32 "
        "{%0,%1,%2,%3}, {%4,%5,%6,%7}, {%8,%9}, {%0,%1,%2,%3};"
        : "+f"(c[0]), "+f"(c[1]), "+f"(c[2]), "+f"(c[3])
        : "r"(a[0]), "r"(a[1]), "r"(a[2]), "r"(a[3]), "r"(b0), "r"(b1));
}

// ---------------- mbarrier ----------------
#define MBAR_INIT(a, c) \
    asm volatile("mbarrier.init.shared.b64 [%0], %1;" :: "r"((uint32_t)(a)), "r"((uint32_t)(c)) : "memory")
#define MBAR_ARRIVE(a) \
    asm volatile("mbarrier.arrive.shared.b64 _, [%0];" :: "r"((uint32_t)(a)) : "memory")
#define MBAR_WAIT(mbar, par) do { \
    uint32_t _m = (uint32_t)(mbar), _p = (uint32_t)(par), _d; \
    asm volatile("{\n\t.reg .pred p;\n\t" \
        "mbarrier.try_wait.parity.acquire.cta.shared::cta.b64 p, [%1], %2;\n\t" \
        "selp.b32 %0, 1, 0, p;\n\t}" : "=r"(_d) : "r"(_m), "r"(_p) : "memory"); \
    if (!_d) { \
        asm volatile("{\n\t.reg .pred P1;\n\t" \
            "WL_%=:\n\t" \
            "mbarrier.try_wait.parity.acquire.cta.shared::cta.b64 P1, [%0], %1, 0x989680;\n\t" \
            "@P1 bra.uni WD_%=;\n\t" \
            "bra.uni WL_%=;\n\t" \
            "WD_%=:\n\t}" :: "r"(_m), "r"(_p) : "memory"); \
    } \
} while(0)

// ---------------- k_prepw: both layers' W^T bf16 hi/lo images ----------------
__global__ void k_prepw(const float* __restrict__ wA1, const float* __restrict__ wA2){
    int n = blockIdx.x, m = blockIdx.y, kk = threadIdx.x;
    const float* W = m ? wA2 : wA1;
    float w = W[kk*EE + n];
    float hf = __bfloat162float(__float2bfloat16(w));
    float lf = w - hf;
    float hn = __shfl_down_sync(0xffffffffu, hf, 1);
    float ln = __shfl_down_sync(0xffffffffu, lf, 1);
    if (!(kk & 1)){
        int off = swz(n, kk);
        *(uint32_t*)((char*)g_wh[m] + off) = packbf(hn, hf);
        *(uint32_t*)((char*)g_wl[m] + off) = packbf(ln, lf);
    }
}

// ---------------- k_init: tb + u0 ----------------
__global__ void k_init(const float* __restrict__ tf, const float* __restrict__ wA1,
                       const float* __restrict__ bA1, const float* __restrict__ q){
    int b = blockIdx.x, j = threadIdx.x;
    float acc = bA1[j];
#pragma unroll 8
    for (int e = 0; e < EE; e++)
        acc += tf[b*EE + e] * wA1[(EE + e)*EE + j];
    g_tb[b*EE + j] = acc;
    g_u0[b*EE + j] = q[b*EE + j];
}

// ---------------- persistent warp-specialized MLP ----------------
#define SW1H 0
#define SW1L 32768
#define SW2H 65536
#define SW2L 98304
#define SA(s)   (131072 + (s)*32768)
#define SBAR    196608
#define SLOG    196640   // float[4][64] hop-0 logit partials
#define SMEMSZ  197664

struct Frag { uint32_t ah[2][4], al[2][4], wh[2][4], wl[2][4]; };

__device__ __forceinline__ void frag_load(Frag& f, uint32_t sAh, uint32_t sAl,
        uint32_t sWh, uint32_t sWl, int wm, int wn, int rsel, int k0){
    ldm4(sAh + swz(wm*32 + rsel,      k0), f.ah[0]);
    ldm4(sAh + swz(wm*32 + 16 + rsel, k0), f.ah[1]);
    ldm4(sAl + swz(wm*32 + rsel,      k0), f.al[0]);
    ldm4(sAl + swz(wm*32 + 16 + rsel, k0), f.al[1]);
    ldm4(sWh + swz(wn*32 + rsel,      k0), f.wh[0]);
    ldm4(sWh + swz(wn*32 + 16 + rsel, k0), f.wh[1]);
    ldm4(sWl + swz(wn*32 + rsel,      k0), f.wl[0]);
    ldm4(sWl + swz(wn*32 + 16 + rsel, k0), f.wl[1]);
}

__device__ __forceinline__ void frag_mma(float acc[2][4][4], const Frag& f){
#pragma unroll
    for (int nt2 = 0; nt2 < 2; nt2++)
#pragma unroll
        for (int mt = 0; mt < 2; mt++){
            mma_bf16(acc[mt][nt2*2],   f.ah[mt], f.wh[nt2][0], f.wh[nt2][2]);
            mma_bf16(acc[mt][nt2*2+1], f.ah[mt], f.wh[nt2][1], f.wh[nt2][3]);
            mma_bf16(acc[mt][nt2*2],   f.ah[mt], f.wl[nt2][0], f.wl[nt2][2]);
            mma_bf16(acc[mt][nt2*2+1], f.ah[mt], f.wl[nt2][1], f.wl[nt2][3]);
            mma_bf16(acc[mt][nt2*2],   f.al[mt], f.wh[nt2][0], f.wh[nt2][2]);
            mma_bf16(acc[mt][nt2*2+1], f.al[mt], f.wh[nt2][1], f.wh[nt2][3]);
        }
}

__device__ __forceinline__ void gemm_fused(uint32_t sAh, uint32_t sAl,
                                           uint32_t sWh, uint32_t sWl,
                                           int wm, int wn, int rsel, int csel,
                                           float acc[2][4][4]){
    Frag f[2];
    frag_load(f[0], sAh, sAl, sWh, sWl, wm, wn, rsel, csel);
#pragma unroll
    for (int ks = 0; ks < 8; ks++){
        if (ks < 7)
            frag_load(f[(ks+1)&1], sAh, sAl, sWh, sWl, wm, wn, rsel, (ks+1)*16 + csel);
        frag_mma(acc, f[ks&1]);
    }
}

__global__ void __launch_bounds__(512, 1)
k_mlp(const int* __restrict__ story, const int* __restrict__ kb_len,
      const int* __restrict__ conv_len, const float* __restrict__ dh,
      const float* __restrict__ C, const float* __restrict__ bA2,
      const float* __restrict__ gp)
{
    extern __shared__ char smem[];
    const uint32_t sb = smem_u32(smem);
    const int tid = threadIdx.x, wid = tid >> 5, lane = tid & 31;
    const int bid = blockIdx.x;

    {
        uint4* s4 = (uint4*)smem;
        for (int i = tid; i < 2048; i += 512){
            s4[i]        = g_wh[0][i];
            s4[i+2048]   = g_wl[0][i];
            s4[i+4096]   = g_wh[1][i];
            s4[i+6144]   = g_wl[1][i];
        }
    }
    if (tid == 0){
        MBAR_INIT(sb + SBAR +  0, 256);   // full[0]
        MBAR_INIT(sb + SBAR +  8, 256);   // full[1]
        MBAR_INIT(sb + SBAR + 16, 256);   // empty[0]
        MBAR_INIT(sb + SBAR + 24, 256);   // empty[1]
    }
    __syncthreads();

    if (wid >= 8){
        // ---------- producer: 8 warps ----------
        const int ptid = tid - 256;
        int it = 0;
        for (int t = bid; t < NTILES; t += NCTA, it++){
            const int s = it & 1;
            const int k = t / 512, g0 = (t & 511) * 64, b = g0 >> 11;
            MBAR_WAIT(sb + SBAR + 16 + s*8, ((it>>1)&1)^1);
            const float* Ck = C + (size_t)k * VE;
            const int kb = __ldg(kb_len + b), cl = __ldg(conv_len + b);
            char* aH = smem + SA(s);
            char* aL = aH + 16384;
#pragma unroll 4
            for (int i = 0; i < 8; i++){
                int item = ptid + (i << 8);
                int r = item >> 5, cq = item & 31;
                int g = g0 + r, m = g & (MM-1);
                const int* st = story + (size_t)g * SS;
                float4 sacc = make_float4(0.f, 0.f, 0.f, 0.f);
#pragma unroll
                for (int j = 0; j < 6; j++){
                    float4 v = __ldg((const float4*)(Ck + (size_t)st[j]*EE) + cq);
                    sacc.x += v.x; sacc.y += v.y; sacc.z += v.z; sacc.w += v.w;
                }
                int idx = m - kb;
                if (idx >= 0 && idx < cl){
                    float4 dv = __ldg((const float4*)(dh + ((size_t)b*LCC + idx)*EE) + cq);
                    sacc.x += dv.x; sacc.y += dv.y; sacc.z += dv.z; sacc.w += dv.w;
                }
                float hx = __bfloat162float(__float2bfloat16(sacc.x));
                float hy = __bfloat162float(__float2bfloat16(sacc.y));
                float hz = __bfloat162float(__float2bfloat16(sacc.z));
                float hw = __bfloat162float(__float2bfloat16(sacc.w));
                int off = swz(r, cq*4);
                uint2 hv, lv;
                hv.x = packbf(hy, hx);           hv.y = packbf(hw, hz);
                lv.x = packbf(sacc.y - hy, sacc.x - hx);
                lv.y = packbf(sacc.w - hw, sacc.z - hz);
                *(uint2*)(aH + off) = hv;
                *(uint2*)(aL + off) = lv;
            }
            MBAR_ARRIVE(sb + SBAR + s*8);
        }
    } else {
        // ---------- consumer: 8 warps ----------
        const int wm = wid & 1, wn = wid >> 1;
        const int rsel = (lane & 7) + (lane & 8);
        const int csel = (lane & 16) >> 1;
        float* slog = (float*)(smem + SLOG);
        int it = 0;
        for (int t = bid; t < NTILES; t += NCTA, it++){
            const int s = it & 1;
            const int k = t / 512, g0 = (t & 511) * 64, b = g0 >> 11;
            const uint32_t sA = sb + SA(s), sAL = sA + 16384;
            MBAR_WAIT(sb + SBAR + s*8, (it>>1)&1);

            float acc[2][4][4];
#pragma unroll
            for (int mt=0; mt<2; mt++)
#pragma unroll
                for (int nt=0; nt<4; nt++)
#pragma unroll
                    for (int i=0; i<4; i++) acc[mt][nt][i] = 0.f;

            gemm_fused(sA, sAL, sb + SW1H, sb + SW1L, wm, wn, rsel, csel, acc);
            asm volatile("bar.sync 1, 256;" ::: "memory");

            // epilogue 1: +tb, lrelu, bf16-split -> overwrite A slot
#pragma unroll
            for (int nt = 0; nt < 4; nt++){
                int gc = wn*32 + nt*8 + (lane & 3)*2;
                float2 tb = *(const float2*)(g_tb + b*EE + gc);
#pragma unroll
                for (int mt = 0; mt < 2; mt++)
#pragma unroll
                    for (int h = 0; h < 2; h++){
                        int rl = wm*32 + mt*16 + (lane >> 2) + h*8;
                        float y0 = acc[mt][nt][h*2]   + tb.x;
                        float y1 = acc[mt][nt][h*2+1] + tb.y;
                        y0 = y0 > 0.f ? y0 : 0.1f*y0;
                        y1 = y1 > 0.f ? y1 : 0.1f*y1;
                        float h0 = __bfloat162float(__float2bfloat16(y0));
                        float h1 = __bfloat162float(__float2bfloat16(y1));
                        int off = swz(rl, gc);
                        *(uint32_t*)(smem + SA(s) + off)         = packbf(h1, h0);
                        *(uint32_t*)(smem + SA(s) + 16384 + off) = packbf(y1 - h1, y0 - h0);
                    }
            }
            asm volatile("bar.sync 1, 256;" ::: "memory");

#pragma unroll
            for (int mt=0; mt<2; mt++)
#pragma unroll
                for (int nt=0; nt<4; nt++)
#pragma unroll
                    for (int i=0; i<4; i++) acc[mt][nt][i] = 0.f;

            gemm_fused(sA, sAL, sb + SW2H, sb + SW2L, wm, wn, rsel, csel, acc);
            MBAR_ARRIVE(sb + SBAR + 16 + s*8);

            if (k != 0){
                // epilogue 2: +bA2, *gp -> g_mg (fp16)
#pragma unroll
                for (int mt = 0; mt < 2; mt++)
#pragma unroll
                    for (int h = 0; h < 2; h++){
                        int rl = wm*32 + mt*16 + (lane >> 2) + h*8;
                        float gv = __ldg(gp + g0 + rl);
                        __half* op = g_mg + (size_t)k*BME + (size_t)(g0 + rl)*EE;
#pragma unroll
                        for (int nt = 0; nt < 4; nt++){
                            int gc = wn*32 + nt*8 + (lane & 3)*2;
                            float2 bv = *(const float2*)(bA2 + gc);
                            float ox = (acc[mt][nt][h*2]   + bv.x) * gv;
                            float oy = (acc[mt][nt][h*2+1] + bv.y) * gv;
                            *(__half2*)(op + gc) = __floats2half2_rn(ox, oy);
                        }
                    }
            } else {
                // hop-0 logits: lp[row] = dot(mg0[row], u0); mg0 never stored
                float lp[4];
#pragma unroll
                for (int mt = 0; mt < 2; mt++)
#pragma unroll
                    for (int h = 0; h < 2; h++){
                        int rl = wm*32 + mt*16 + (lane >> 2) + h*8;
                        float gv = __ldg(gp + g0 + rl);
                        float p = 0.f;
#pragma unroll
                        for (int nt = 0; nt < 4; nt++){
                            int gc = wn*32 + nt*8 + (lane & 3)*2;
                            float2 bv = *(const float2*)(bA2 + gc);
                            float2 u0 = *(const float2*)(g_u0 + b*EE + gc);
                            float ox = (acc[mt][nt][h*2]   + bv.x) * gv;
                            float oy = (acc[mt][nt][h*2+1] + bv.y) * gv;
                            p += ox*u0.x + oy*u0.y;
                        }
                        lp[mt*2 + h] = p;
                    }
#pragma unroll
                for (int i = 0; i < 4; i++){
                    lp[i] += __shfl_xor_sync(0xffffffffu, lp[i], 1);
                    lp[i] += __shfl_xor_sync(0xffffffffu, lp[i], 2);
                }
                if ((lane & 3) == 0){
#pragma unroll
                    for (int mt = 0; mt < 2; mt++)
#pragma unroll
                        for (int h = 0; h < 2; h++){
                            int rl = wm*32 + mt*16 + (lane >> 2) + h*8;
                            slog[wn*64 + rl] = lp[mt*2 + h];
                        }
                }
                asm volatile("bar.sync 1, 256;" ::: "memory");
                if (tid < 64)
                    g_logits[g0 + tid] = slog[tid] + slog[64+tid] + slog[128+tid] + slog[192+tid];
            }
        }
    }
}

// ---------------- phase 2 ----------------
// logits for hop k (k=1,2): u rebuilt in-block from u0 + part buffers
__global__ void k_logits(int k, int nparts, float* __restrict__ extra){
    __shared__ float su[EE];
    int tid = threadIdx.x;
    int gw0 = (blockIdx.x * blockDim.x) >> 5;
    int b = (gw0 * 16) >> 11;
    if (tid < EE){
        float v = g_u0[b*EE + tid];
        for (int p = 0; p < nparts; p++)
#pragma unroll
            for (int c = 0; c < 16; c++)
                v += g_part[p][c][b*EE + tid];
        su[tid] = v;
    }
    __syncthreads();
    int gw = (blockIdx.x * blockDim.x + tid) >> 5;
    int lane = tid & 31;
    int sub = lane & 15, half = lane >> 4;
    int g0 = gw * 16;
    float4 ua = *(const float4*)(su + sub*8);
    float4 ub = *(const float4*)(su + sub*8 + 4);
    const __half* mg = g_mg + (size_t)k*BME + (size_t)g0*EE;

    uint4 rv[8];
#pragma unroll
    for (int i = 0; i < 8; i++){
        int row = i*2 + half;
        rv[i] = *(const uint4*)(mg + (size_t)row*EE + sub*8);
    }
    float p[8];
#pragma unroll
    for (int i = 0; i < 8; i++){
        float2 x0 = __half22float2(*(__half2*)&rv[i].x);
        float2 x1 = __half22float2(*(__half2*)&rv[i].y);
        float2 x2 = __half22float2(*(__half2*)&rv[i].z);
        float2 x3 = __half22float2(*(__half2*)&rv[i].w);
        p[i] = x0.x*ua.x + x0.y*ua.y + x1.x*ua.z + x1.y*ua.w
             + x2.x*ub.x + x2.y*ub.y + x3.x*ub.z + x3.y*ub.w;
    }
#pragma unroll
    for (int i = 0; i < 8; i++)
#pragma unroll
        for (int o = 8; o; o >>= 1) p[i] += __shfl_xor_sync(0xffffffffu, p[i], o);
    if (!sub){
#pragma unroll
        for (int i = 0; i < 8; i++){
            int row = g0 + i*2 + half;
            g_logits[row] = p[i];
            if (extra) extra[row] = p[i];
        }
    }
}

// warp-shuffle softmax
__global__ void k_softmax(float* __restrict__ extra){
    __shared__ float wred[16];
    __shared__ float bc;
    int b = blockIdx.x, tid = threadIdx.x, w = tid >> 5, lane = tid & 31;
    const float* l = g_logits + b*MM;
    float v[4];
#pragma unroll
    for (int i = 0; i < 4; i++) v[i] = l[tid + i*512];
    float mx = fmaxf(fmaxf(v[0], v[1]), fmaxf(v[2], v[3]));
#pragma unroll
    for (int o = 16; o; o >>= 1) mx = fmaxf(mx, __shfl_xor_sync(0xffffffffu, mx, o));
    if (!lane) wred[w] = mx;
    __syncthreads();
    if (tid < 32){
        float m = (lane < 16) ? wred[lane] : -3.4e38f;
#pragma unroll
        for (int o = 8; o; o >>= 1) m = fmaxf(m, __shfl_xor_sync(0xffffffffu, m, o));
        if (!lane) bc = m;
    }
    __syncthreads();
    mx = bc;
    float e[4], ss = 0.f;
#pragma unroll
    for (int i = 0; i < 4; i++){ e[i] = expf(v[i] - mx); ss += e[i]; }
#pragma unroll
    for (int o = 16; o; o >>= 1) ss += __shfl_xor_sync(0xffffffffu, ss, o);
    if (!lane) wred[w] = ss;
    __syncthreads();
    if (tid < 32){
        float m = (lane < 16) ? wred[lane] : 0.f;
#pragma unroll
        for (int o = 8; o; o >>= 1) m += __shfl_xor_sync(0xffffffffu, m, o);
        if (!lane) bc = m;
    }
    __syncthreads();
    float inv = 1.f / bc;
#pragma unroll
    for (int i = 0; i < 4; i++){
        float sv = e[i] * inv;
        g_soft[b*MM + tid + i*512] = sv;
        if (extra) extra[b*MM + tid + i*512] = sv;
    }
}

// upart: mg[k] weighted by soft -> g_part[pbuf]
__global__ void k_upart(int k, int pbuf){
    __shared__ float red[8][EE];
    int chunk = blockIdx.x, b = blockIdx.y;
    int tid = threadIdx.x, w = tid >> 5, lane = tid & 31;
    int sub = lane & 15, half = lane >> 4;
    int m0 = chunk*128 + w*16;
    const __half* mg = g_mg + (size_t)k*BME + ((size_t)(b*MM + m0))*EE;
    const float* sp = g_soft + b*MM + m0;
    float a[8] = {0.f,0.f,0.f,0.f,0.f,0.f,0.f,0.f};
#pragma unroll
    for (int i = 0; i < 8; i++){
        int row = i*2 + half;
        float s = sp[row];
        uint4 rv = *(const uint4*)(mg + (size_t)row*EE + sub*8);
        float2 x0 = __half22float2(*(__half2*)&rv.x);
        float2 x1 = __half22float2(*(__half2*)&rv.y);
        float2 x2 = __half22float2(*(__half2*)&rv.z);
        float2 x3 = __half22float2(*(__half2*)&rv.w);
        a[0] += s*x0.x; a[1] += s*x0.y; a[2] += s*x1.x; a[3] += s*x1.y;
        a[4] += s*x2.x; a[5] += s*x2.y; a[6] += s*x3.x; a[7] += s*x3.y;
    }
#pragma unroll
    for (int j = 0; j < 8; j++) a[j] += __shfl_xor_sync(0xffffffffu, a[j], 16);
    if (!half){
#pragma unroll
        for (int j = 0; j < 8; j++) red[w][sub*8 + j] = a[j];
    }
    __syncthreads();
    if (tid < EE){
        float acc = 0.f;
#pragma unroll
        for (int i = 0; i < 8; i++) acc += red[i][tid];
        g_part[pbuf][chunk][b*EE + tid] = acc;
    }
}

// ---------------- launch ----------------
extern "C" void kernel_launch(void* const* d_in, const int* in_sizes, int n_in,
                              void* d_out, int out_size){
    const int*   story    = (const int*)  d_in[0];
    const int*   kb_len   = (const int*)  d_in[1];
    const int*   conv_len = (const int*)  d_in[2];
    const float* dh       = (const float*)d_in[4];
    const float* tf       = (const float*)d_in[5];
    const float* q        = (const float*)d_in[6];
    const float* gp       = (const float*)d_in[7];
    const float* C        = (const float*)d_in[8];
    const float* wA1      = (const float*)d_in[9];
    const float* bA1      = (const float*)d_in[10];
    const float* wA2      = (const float*)d_in[11];
    const float* bA2      = (const float*)d_in[12];
    float* out = (float*)d_out;   // [0:BM) prob_soft, [BM:2BM) prob_logits

    cudaFuncSetAttribute(k_mlp, cudaFuncAttributeMaxDynamicSharedMemorySize, SMEMSZ);

    k_prepw <<<dim3(128,2), 128>>>(wA1, wA2);
    k_init  <<<BB, EE>>>(tf, wA1, bA1, q);
    k_mlp   <<<NCTA, 512, SMEMSZ>>>(story, kb_len, conv_len, dh, C, bA2, gp);

    // hop 0: logits fused into k_mlp
    k_softmax<<<BB, 512>>>(nullptr);
    k_upart  <<<dim3(16, BB), 256>>>(1, 0);          // part0 = soft0 @ mg1
    // hop 1: u1 = u0 + part0 (rebuilt inside k_logits)
    k_logits <<<256, 256>>>(1, 1, nullptr);
    k_softmax<<<BB, 512>>>(nullptr);
    k_upart  <<<dim3(16, BB), 256>>>(2, 1);          // part1 = soft1 @ mg2
    // hop 2: u2 = u0 + part0 + part1 (final outputs)
    k_logits <<<256, 256>>>(2, 2, out + BM);
    k_softmax<<<BB, 512>>>(out);
}

// round 16
// speedup vs baseline: 1.3322x; 1.0057x over previous
#include <cuda_runtime.h>
#include <cuda_bf16.h>
#include <cuda_fp16.h>
#include <cstdint>

#define BB 16
#define MM 2048
#define SS 6
#define EE 128
#define LCC 512
#define VV 32000
#define BM (BB*MM)        // 32768
#define VE (VV*EE)
#define BME (BM*EE)
#define NTILES 1536       // 3 k * 512 tiles of 64 rows
#define NCTA 148

// ---------------- static device scratch ----------------
__device__ __half g_mg[3u*BME];     // MLP(bag)*gp, fp16, [k][g][e] (k=0 never stored)
__device__ float g_tb[BB*EE];       // tf@wA1_bottom + bA1
__device__ float g_u0[BB*EE];       // u0 = q
__device__ float g_logits[BM];
__device__ float g_soft[BM];
__device__ float g_part[2][16][BB*EE];
__device__ uint4 g_wh[2][2048];     // W^T bf16-hi images, swizzled (32KB each)
__device__ uint4 g_wl[2][2048];     // bf16-lo images

// ---------------- helpers ----------------
__device__ __forceinline__ uint32_t smem_u32(const void* p){
    uint32_t a;
    asm("{ .reg .u64 t; cvta.to.shared.u64 t, %1; cvt.u32.u64 %0, t; }" : "=r"(a) : "l"(p));
    return a;
}
__device__ __forceinline__ uint32_t packbf(float hi, float lo){
    uint32_t r;
    asm("cvt.rn.bf16x2.f32 %0, %1, %2;" : "=r"(r) : "f"(hi), "f"(lo));
    return r;
}
// swizzled byte offset of bf16 (r, c) in an Nx128 tile (256B rows); keeps chunk bit 3.
__device__ __forceinline__ int swz(int r, int c){
    int ch = c >> 3;
    ch = (ch & 8) | ((ch ^ r) & 7);
    return r*256 + ch*16 + (c & 7)*2;
}
__device__ __forceinline__ void ldm4(uint32_t addr, uint32_t r[4]){
    asm volatile("ldmatrix.sync.aligned.m8n8.x4.shared.b16 {%0,%1,%2,%3}, [%4];"
        : "=r"(r[0]), "=r"(r[1]), "=r"(r[2]), "=r"(r[3]) : "r"(addr));
}
__device__ __forceinline__ void mma_bf16(float c[4], const uint32_t a[4], uint32_t b0, uint32_t b1){
    asm volatile("mma.sync.aligned.m16n8k16.row.col.f32.bf16.bf16.f32 "
        "{%0,%1,%2,%3}, {%4,%5,%6,%7}, {%8,%9}, {%0,%1,%2,%3};"
        : "+f"(c[0]), "+f"(c[1]), "+f"(c[2]), "+f"(c[3])
        : "r"(a[0]), "r"(a[1]), "r"(a[2]), "r"(a[3]), "r"(b0), "r"(b1));
}

// ---------------- mbarrier ----------------
#define MBAR_INIT(a, c) \
    asm volatile("mbarrier.init.shared.b64 [%0], %1;" :: "r"((uint32_t)(a)), "r"((uint32_t)(c)) : "memory")
#define MBAR_ARRIVE(a) \
    asm volatile("mbarrier.arrive.shared.b64 _, [%0];" :: "r"((uint32_t)(a)) : "memory")
#define MBAR_WAIT(mbar, par) do { \
    uint32_t _m = (uint32_t)(mbar), _p = (uint32_t)(par), _d; \
    asm volatile("{\n\t.reg .pred p;\n\t" \
        "mbarrier.try_wait.parity.acquire.cta.shared::cta.b64 p, [%1], %2;\n\t" \
        "selp.b32 %0, 1, 0, p;\n\t}" : "=r"(_d) : "r"(_m), "r"(_p) : "memory"); \
    if (!_d) { \
        asm volatile("{\n\t.reg .pred P1;\n\t" \
            "WL_%=:\n\t" \
            "mbarrier.try_wait.parity.acquire.cta.shared::cta.b64 P1, [%0], %1, 0x989680;\n\t" \
            "@P1 bra.uni WD_%=;\n\t" \
            "bra.uni WL_%=;\n\t" \
            "WD_%=:\n\t}" :: "r"(_m), "r"(_p) : "memory"); \
    } \
} while(0)

// ---------------- k_prepw: both layers' W^T bf16 hi/lo images ----------------
__global__ void k_prepw(const float* __restrict__ wA1, const float* __restrict__ wA2){
    int n = blockIdx.x, m = blockIdx.y, kk = threadIdx.x;
    const float* W = m ? wA2 : wA1;
    float w = W[kk*EE + n];
    float hf = __bfloat162float(__float2bfloat16(w));
    float lf = w - hf;
    float hn = __shfl_down_sync(0xffffffffu, hf, 1);
    float ln = __shfl_down_sync(0xffffffffu, lf, 1);
    if (!(kk & 1)){
        int off = swz(n, kk);
        *(uint32_t*)((char*)g_wh[m] + off) = packbf(hn, hf);
        *(uint32_t*)((char*)g_wl[m] + off) = packbf(ln, lf);
    }
}

// ---------------- k_init: tb + u0 ----------------
__global__ void k_init(const float* __restrict__ tf, const float* __restrict__ wA1,
                       const float* __restrict__ bA1, const float* __restrict__ q){
    int b = blockIdx.x, j = threadIdx.x;
    float acc = bA1[j];
#pragma unroll 8
    for (int e = 0; e < EE; e++)
        acc += tf[b*EE + e] * wA1[(EE + e)*EE + j];
    g_tb[b*EE + j] = acc;
    g_u0[b*EE + j] = q[b*EE + j];
}

// ---------------- persistent warp-specialized MLP (unchanged from R15) ----------------
#define SW1H 0
#define SW1L 32768
#define SW2H 65536
#define SW2L 98304
#define SA(s)   (131072 + (s)*32768)
#define SBAR    196608
#define SLOG    196640   // float[4][64] hop-0 logit partials
#define SMEMSZ  197664

struct Frag { uint32_t ah[2][4], al[2][4], wh[2][4], wl[2][4]; };

__device__ __forceinline__ void frag_load(Frag& f, uint32_t sAh, uint32_t sAl,
        uint32_t sWh, uint32_t sWl, int wm, int wn, int rsel, int k0){
    ldm4(sAh + swz(wm*32 + rsel,      k0), f.ah[0]);
    ldm4(sAh + swz(wm*32 + 16 + rsel, k0), f.ah[1]);
    ldm4(sAl + swz(wm*32 + rsel,      k0), f.al[0]);
    ldm4(sAl + swz(wm*32 + 16 + rsel, k0), f.al[1]);
    ldm4(sWh + swz(wn*32 + rsel,      k0), f.wh[0]);
    ldm4(sWh + swz(wn*32 + 16 + rsel, k0), f.wh[1]);
    ldm4(sWl + swz(wn*32 + rsel,      k0), f.wl[0]);
    ldm4(sWl + swz(wn*32 + 16 + rsel, k0), f.wl[1]);
}

__device__ __forceinline__ void frag_mma(float acc[2][4][4], const Frag& f){
#pragma unroll
    for (int nt2 = 0; nt2 < 2; nt2++)
#pragma unroll
        for (int mt = 0; mt < 2; mt++){
            mma_bf16(acc[mt][nt2*2],   f.ah[mt], f.wh[nt2][0], f.wh[nt2][2]);
            mma_bf16(acc[mt][nt2*2+1], f.ah[mt], f.wh[nt2][1], f.wh[nt2][3]);
            mma_bf16(acc[mt][nt2*2],   f.ah[mt], f.wl[nt2][0], f.wl[nt2][2]);
            mma_bf16(acc[mt][nt2*2+1], f.ah[mt], f.wl[nt2][1], f.wl[nt2][3]);
            mma_bf16(acc[mt][nt2*2],   f.al[mt], f.wh[nt2][0], f.wh[nt2][2]);
            mma_bf16(acc[mt][nt2*2+1], f.al[mt], f.wh[nt2][1], f.wh[nt2][3]);
        }
}

__device__ __forceinline__ void gemm_fused(uint32_t sAh, uint32_t sAl,
                                           uint32_t sWh, uint32_t sWl,
                                           int wm, int wn, int rsel, int csel,
                                           float acc[2][4][4]){
    Frag f[2];
    frag_load(f[0], sAh, sAl, sWh, sWl, wm, wn, rsel, csel);
#pragma unroll
    for (int ks = 0; ks < 8; ks++){
        if (ks < 7)
            frag_load(f[(ks+1)&1], sAh, sAl, sWh, sWl, wm, wn, rsel, (ks+1)*16 + csel);
        frag_mma(acc, f[ks&1]);
    }
}

__global__ void __launch_bounds__(512, 1)
k_mlp(const int* __restrict__ story, const int* __restrict__ kb_len,
      const int* __restrict__ conv_len, const float* __restrict__ dh,
      const float* __restrict__ C, const float* __restrict__ bA2,
      const float* __restrict__ gp)
{
    extern __shared__ char smem[];
    const uint32_t sb = smem_u32(smem);
    const int tid = threadIdx.x, wid = tid >> 5, lane = tid & 31;
    const int bid = blockIdx.x;

    {
        uint4* s4 = (uint4*)smem;
        for (int i = tid; i < 2048; i += 512){
            s4[i]        = g_wh[0][i];
            s4[i+2048]   = g_wl[0][i];
            s4[i+4096]   = g_wh[1][i];
            s4[i+6144]   = g_wl[1][i];
        }
    }
    if (tid == 0){
        MBAR_INIT(sb + SBAR +  0, 256);   // full[0]
        MBAR_INIT(sb + SBAR +  8, 256);   // full[1]
        MBAR_INIT(sb + SBAR + 16, 256);   // empty[0]
        MBAR_INIT(sb + SBAR + 24, 256);   // empty[1]
    }
    __syncthreads();

    if (wid >= 8){
        // ---------- producer: 8 warps ----------
        const int ptid = tid - 256;
        int it = 0;
        for (int t = bid; t < NTILES; t += NCTA, it++){
            const int s = it & 1;
            const int k = t / 512, g0 = (t & 511) * 64, b = g0 >> 11;
            MBAR_WAIT(sb + SBAR + 16 + s*8, ((it>>1)&1)^1);
            const float* Ck = C + (size_t)k * VE;
            const int kb = __ldg(kb_len + b), cl = __ldg(conv_len + b);
            char* aH = smem + SA(s);
            char* aL = aH + 16384;
#pragma unroll 4
            for (int i = 0; i < 8; i++){
                int item = ptid + (i << 8);
                int r = item >> 5, cq = item & 31;
                int g = g0 + r, m = g & (MM-1);
                const int* st = story + (size_t)g * SS;
                float4 sacc = make_float4(0.f, 0.f, 0.f, 0.f);
#pragma unroll
                for (int j = 0; j < 6; j++){
                    float4 v = __ldg((const float4*)(Ck + (size_t)st[j]*EE) + cq);
                    sacc.x += v.x; sacc.y += v.y; sacc.z += v.z; sacc.w += v.w;
                }
                int idx = m - kb;
                if (idx >= 0 && idx < cl){
                    float4 dv = __ldg((const float4*)(dh + ((size_t)b*LCC + idx)*EE) + cq);
                    sacc.x += dv.x; sacc.y += dv.y; sacc.z += dv.z; sacc.w += dv.w;
                }
                float hx = __bfloat162float(__float2bfloat16(sacc.x));
                float hy = __bfloat162float(__float2bfloat16(sacc.y));
                float hz = __bfloat162float(__float2bfloat16(sacc.z));
                float hw = __bfloat162float(__float2bfloat16(sacc.w));
                int off = swz(r, cq*4);
                uint2 hv, lv;
                hv.x = packbf(hy, hx);           hv.y = packbf(hw, hz);
                lv.x = packbf(sacc.y - hy, sacc.x - hx);
                lv.y = packbf(sacc.w - hw, sacc.z - hz);
                *(uint2*)(aH + off) = hv;
                *(uint2*)(aL + off) = lv;
            }
            MBAR_ARRIVE(sb + SBAR + s*8);
        }
    } else {
        // ---------- consumer: 8 warps ----------
        const int wm = wid & 1, wn = wid >> 1;
        const int rsel = (lane & 7) + (lane & 8);
        const int csel = (lane & 16) >> 1;
        float* slog = (float*)(smem + SLOG);
        int it = 0;
        for (int t = bid; t < NTILES; t += NCTA, it++){
            const int s = it & 1;
            const int k = t / 512, g0 = (t & 511) * 64, b = g0 >> 11;
            const uint32_t sA = sb + SA(s), sAL = sA + 16384;
            MBAR_WAIT(sb + SBAR + s*8, (it>>1)&1);

            float acc[2][4][4];
#pragma unroll
            for (int mt=0; mt<2; mt++)
#pragma unroll
                for (int nt=0; nt<4; nt++)
#pragma unroll
                    for (int i=0; i<4; i++) acc[mt][nt][i] = 0.f;

            gemm_fused(sA, sAL, sb + SW1H, sb + SW1L, wm, wn, rsel, csel, acc);
            asm volatile("bar.sync 1, 256;" ::: "memory");

            // epilogue 1: +tb, lrelu, bf16-split -> overwrite A slot
#pragma unroll
            for (int nt = 0; nt < 4; nt++){
                int gc = wn*32 + nt*8 + (lane & 3)*2;
                float2 tb = *(const float2*)(g_tb + b*EE + gc);
#pragma unroll
                for (int mt = 0; mt < 2; mt++)
#pragma unroll
                    for (int h = 0; h < 2; h++){
                        int rl = wm*32 + mt*16 + (lane >> 2) + h*8;
                        float y0 = acc[mt][nt][h*2]   + tb.x;
                        float y1 = acc[mt][nt][h*2+1] + tb.y;
                        y0 = y0 > 0.f ? y0 : 0.1f*y0;
                        y1 = y1 > 0.f ? y1 : 0.1f*y1;
                        float h0 = __bfloat162float(__float2bfloat16(y0));
                        float h1 = __bfloat162float(__float2bfloat16(y1));
                        int off = swz(rl, gc);
                        *(uint32_t*)(smem + SA(s) + off)         = packbf(h1, h0);
                        *(uint32_t*)(smem + SA(s) + 16384 + off) = packbf(y1 - h1, y0 - h0);
                    }
            }
            asm volatile("bar.sync 1, 256;" ::: "memory");

#pragma unroll
            for (int mt=0; mt<2; mt++)
#pragma unroll
                for (int nt=0; nt<4; nt++)
#pragma unroll
                    for (int i=0; i<4; i++) acc[mt][nt][i] = 0.f;

            gemm_fused(sA, sAL, sb + SW2H, sb + SW2L, wm, wn, rsel, csel, acc);
            MBAR_ARRIVE(sb + SBAR + 16 + s*8);

            if (k != 0){
                // epilogue 2: +bA2, *gp -> g_mg (fp16)
#pragma unroll
                for (int mt = 0; mt < 2; mt++)
#pragma unroll
                    for (int h = 0; h < 2; h++){
                        int rl = wm*32 + mt*16 + (lane >> 2) + h*8;
                        float gv = __ldg(gp + g0 + rl);
                        __half* op = g_mg + (size_t)k*BME + (size_t)(g0 + rl)*EE;
#pragma unroll
                        for (int nt = 0; nt < 4; nt++){
                            int gc = wn*32 + nt*8 + (lane & 3)*2;
                            float2 bv = *(const float2*)(bA2 + gc);
                            float ox = (acc[mt][nt][h*2]   + bv.x) * gv;
                            float oy = (acc[mt][nt][h*2+1] + bv.y) * gv;
                            *(__half2*)(op + gc) = __floats2half2_rn(ox, oy);
                        }
                    }
            } else {
                // hop-0 logits: lp[row] = dot(mg0[row], u0); mg0 never stored
                float lp[4];
#pragma unroll
                for (int mt = 0; mt < 2; mt++)
#pragma unroll
                    for (int h = 0; h < 2; h++){
                        int rl = wm*32 + mt*16 + (lane >> 2) + h*8;
                        float gv = __ldg(gp + g0 + rl);
                        float p = 0.f;
#pragma unroll
                        for (int nt = 0; nt < 4; nt++){
                            int gc = wn*32 + nt*8 + (lane & 3)*2;
                            float2 bv = *(const float2*)(bA2 + gc);
                            float2 u0 = *(const float2*)(g_u0 + b*EE + gc);
                            float ox = (acc[mt][nt][h*2]   + bv.x) * gv;
                            float oy = (acc[mt][nt][h*2+1] + bv.y) * gv;
                            p += ox*u0.x + oy*u0.y;
                        }
                        lp[mt*2 + h] = p;
                    }
#pragma unroll
                for (int i = 0; i < 4; i++){
                    lp[i] += __shfl_xor_sync(0xffffffffu, lp[i], 1);
                    lp[i] += __shfl_xor_sync(0xffffffffu, lp[i], 2);
                }
                if ((lane & 3) == 0){
#pragma unroll
                    for (int mt = 0; mt < 2; mt++)
#pragma unroll
                        for (int h = 0; h < 2; h++){
                            int rl = wm*32 + mt*16 + (lane >> 2) + h*8;
                            slog[wn*64 + rl] = lp[mt*2 + h];
                        }
                }
                asm volatile("bar.sync 1, 256;" ::: "memory");
                if (tid < 64)
                    g_logits[g0 + tid] = slog[tid] + slog[64+tid] + slog[128+tid] + slog[192+tid];
            }
        }
    }
}

// ---------------- phase 2 ----------------
// logits for hop k (k=1,2): u rebuilt in-block from u0 + part buffers
__global__ void k_logits(int k, int nparts, float* __restrict__ extra){
    __shared__ float su[EE];
    int tid = threadIdx.x;
    int gw0 = (blockIdx.x * blockDim.x) >> 5;
    int b = (gw0 * 16) >> 11;
    if (tid < EE){
        float v = g_u0[b*EE + tid];
        for (int p = 0; p < nparts; p++)
#pragma unroll
            for (int c = 0; c < 16; c++)
                v += g_part[p][c][b*EE + tid];
        su[tid] = v;
    }
    __syncthreads();
    int gw = (blockIdx.x * blockDim.x + tid) >> 5;
    int lane = tid & 31;
    int sub = lane & 15, half = lane >> 4;
    int g0 = gw * 16;
    float4 ua = *(const float4*)(su + sub*8);
    float4 ub = *(const float4*)(su + sub*8 + 4);
    const __half* mg = g_mg + (size_t)k*BME + (size_t)g0*EE;

    uint4 rv[8];
#pragma unroll
    for (int i = 0; i < 8; i++){
        int row = i*2 + half;
        rv[i] = *(const uint4*)(mg + (size_t)row*EE + sub*8);
    }
    float p[8];
#pragma unroll
    for (int i = 0; i < 8; i++){
        float2 x0 = __half22float2(*(__half2*)&rv[i].x);
        float2 x1 = __half22float2(*(__half2*)&rv[i].y);
        float2 x2 = __half22float2(*(__half2*)&rv[i].z);
        float2 x3 = __half22float2(*(__half2*)&rv[i].w);
        p[i] = x0.x*ua.x + x0.y*ua.y + x1.x*ua.z + x1.y*ua.w
             + x2.x*ub.x + x2.y*ub.y + x3.x*ub.z + x3.y*ub.w;
    }
#pragma unroll
    for (int i = 0; i < 8; i++)
#pragma unroll
        for (int o = 8; o; o >>= 1) p[i] += __shfl_xor_sync(0xffffffffu, p[i], o);
    if (!sub){
#pragma unroll
        for (int i = 0; i < 8; i++){
            int row = g0 + i*2 + half;
            g_logits[row] = p[i];
            if (extra) extra[row] = p[i];
        }
    }
}

// final-output softmax (hop 2 only)
__global__ void k_softmax(float* __restrict__ extra){
    __shared__ float wred[16];
    __shared__ float bc;
    int b = blockIdx.x, tid = threadIdx.x, w = tid >> 5, lane = tid & 31;
    const float* l = g_logits + b*MM;
    float v[4];
#pragma unroll
    for (int i = 0; i < 4; i++) v[i] = l[tid + i*512];
    float mx = fmaxf(fmaxf(v[0], v[1]), fmaxf(v[2], v[3]));
#pragma unroll
    for (int o = 16; o; o >>= 1) mx = fmaxf(mx, __shfl_xor_sync(0xffffffffu, mx, o));
    if (!lane) wred[w] = mx;
    __syncthreads();
    if (tid < 32){
        float m = (lane < 16) ? wred[lane] : -3.4e38f;
#pragma unroll
        for (int o = 8; o; o >>= 1) m = fmaxf(m, __shfl_xor_sync(0xffffffffu, m, o));
        if (!lane) bc = m;
    }
    __syncthreads();
    mx = bc;
    float e[4], ss = 0.f;
#pragma unroll
    for (int i = 0; i < 4; i++){ e[i] = expf(v[i] - mx); ss += e[i]; }
#pragma unroll
    for (int o = 16; o; o >>= 1) ss += __shfl_xor_sync(0xffffffffu, ss, o);
    if (!lane) wred[w] = ss;
    __syncthreads();
    if (tid < 32){
        float m = (lane < 16) ? wred[lane] : 0.f;
#pragma unroll
        for (int o = 8; o; o >>= 1) m += __shfl_xor_sync(0xffffffffu, m, o);
        if (!lane) bc = m;
    }
    __syncthreads();
    float inv = 1.f / bc;
#pragma unroll
    for (int i = 0; i < 4; i++){
        float sv = e[i] * inv;
        g_soft[b*MM + tid + i*512] = sv;
        if (extra) extra[b*MM + tid + i*512] = sv;
    }
}

// fused softmax + upart: per-block inline softmax normalization over the batch's
// 2048 logits, then weighted partial sum of mg[k] -> g_part[pbuf]
__global__ void k_upartS(int k, int pbuf){
    __shared__ float red[8][EE];
    __shared__ float wred[8];
    __shared__ float bc[2];
    int chunk = blockIdx.x, b = blockIdx.y;
    int tid = threadIdx.x, w = tid >> 5, lane = tid & 31;
    const float* l = g_logits + b*MM;

    // max over 2048 logits (8 per thread)
    float v[8];
#pragma unroll
    for (int i = 0; i < 8; i++) v[i] = l[tid + i*256];
    float mx = v[0];
#pragma unroll
    for (int i = 1; i < 8; i++) mx = fmaxf(mx, v[i]);
#pragma unroll
    for (int o = 16; o; o >>= 1) mx = fmaxf(mx, __shfl_xor_sync(0xffffffffu, mx, o));
    if (!lane) wred[w] = mx;
    __syncthreads();
    if (tid < 32){
        float m = (lane < 8) ? wred[lane] : -3.4e38f;
#pragma unroll
        for (int o = 4; o; o >>= 1) m = fmaxf(m, __shfl_xor_sync(0xffffffffu, m, o));
        if (!lane) bc[0] = m;
    }
    __syncthreads();
    mx = bc[0];
    // sum of exp
    float ss = 0.f;
#pragma unroll
    for (int i = 0; i < 8; i++) ss += expf(v[i] - mx);
#pragma unroll
    for (int o = 16; o; o >>= 1) ss += __shfl_xor_sync(0xffffffffu, ss, o);
    if (!lane) wred[w] = ss;
    __syncthreads();
    if (tid < 32){
        float m = (lane < 8) ? wred[lane] : 0.f;
#pragma unroll
        for (int o = 4; o; o >>= 1) m += __shfl_xor_sync(0xffffffffu, m, o);
        if (!lane) bc[1] = m;
    }
    __syncthreads();
    const float inv = 1.f / bc[1];

    // weighted partial with inline softmax
    int sub = lane & 15, half = lane >> 4;
    int m0 = chunk*128 + w*16;
    const __half* mg = g_mg + (size_t)k*BME + ((size_t)(b*MM + m0))*EE;
    const float* sp = g_logits + b*MM + m0;
    float a[8] = {0.f,0.f,0.f,0.f,0.f,0.f,0.f,0.f};
#pragma unroll
    for (int i = 0; i < 8; i++){
        int row = i*2 + half;
        float s = expf(sp[row] - mx) * inv;
        uint4 rv = *(const uint4*)(mg + (size_t)row*EE + sub*8);
        float2 x0 = __half22float2(*(__half2*)&rv.x);
        float2 x1 = __half22float2(*(__half2*)&rv.y);
        float2 x2 = __half22float2(*(__half2*)&rv.z);
        float2 x3 = __half22float2(*(__half2*)&rv.w);
        a[0] += s*x0.x; a[1] += s*x0.y; a[2] += s*x1.x; a[3] += s*x1.y;
        a[4] += s*x2.x; a[5] += s*x2.y; a[6] += s*x3.x; a[7] += s*x3.y;
    }
#pragma unroll
    for (int j = 0; j < 8; j++) a[j] += __shfl_xor_sync(0xffffffffu, a[j], 16);
    if (!half){
#pragma unroll
        for (int j = 0; j < 8; j++) red[w][sub*8 + j] = a[j];
    }
    __syncthreads();
    if (tid < EE){
        float acc = 0.f;
#pragma unroll
        for (int i = 0; i < 8; i++) acc += red[i][tid];
        g_part[pbuf][chunk][b*EE + tid] = acc;
    }
}

// ---------------- launch ----------------
extern "C" void kernel_launch(void* const* d_in, const int* in_sizes, int n_in,
                              void* d_out, int out_size){
    const int*   story    = (const int*)  d_in[0];
    const int*   kb_len   = (const int*)  d_in[1];
    const int*   conv_len = (const int*)  d_in[2];
    const float* dh       = (const float*)d_in[4];
    const float* tf       = (const float*)d_in[5];
    const float* q        = (const float*)d_in[6];
    const float* gp       = (const float*)d_in[7];
    const float* C        = (const float*)d_in[8];
    const float* wA1      = (const float*)d_in[9];
    const float* bA1      = (const float*)d_in[10];
    const float* wA2      = (const float*)d_in[11];
    const float* bA2      = (const float*)d_in[12];
    float* out = (float*)d_out;   // [0:BM) prob_soft, [BM:2BM) prob_logits

    cudaFuncSetAttribute(k_mlp, cudaFuncAttributeMaxDynamicSharedMemorySize, SMEMSZ);

    k_prepw <<<dim3(128,2), 128>>>(wA1, wA2);
    k_init  <<<BB, EE>>>(tf, wA1, bA1, q);
    k_mlp   <<<NCTA, 512, SMEMSZ>>>(story, kb_len, conv_len, dh, C, bA2, gp);

    // hop 0: logits fused into k_mlp; softmax fused into upart
    k_upartS <<<dim3(16, BB), 256>>>(1, 0);          // part0 = softmax(logits0) @ mg1
    // hop 1: u1 = u0 + part0 (rebuilt inside k_logits); softmax fused into upart
    k_logits <<<256, 256>>>(1, 1, nullptr);
    k_upartS <<<dim3(16, BB), 256>>>(2, 1);          // part1 = softmax(logits1) @ mg2
    // hop 2: u2 = u0 + part0 + part1 (final outputs)
    k_logits <<<256, 256>>>(2, 2, out + BM);
    k_softmax<<<BB, 512>>>(out);
}